// round 4
// baseline (speedup 1.0000x reference)
#include <cuda_runtime.h>
#include <cstdint>

#define N_NODES 100000
#define IN_CH   1280
#define G_CH    128
#define HID     512
#define NCLS    79

// ---------------- scratch (device globals: no allocation allowed) ----------------
__device__ float g_xw [(size_t)N_NODES * G_CH];   // x @ W_gcn
__device__ float g_agg[(size_t)N_NODES * G_CH];   // aggregated messages -> x1
__device__ float g_deg[N_NODES];                  // degree -> dinv (in place)
__device__ int   g_i64mode;                       // 1 if edge_index is int64, else int32

// ---------------- edge dtype probe ----------------
// If interpreting the buffer as int64 yields only plausible node ids, it's int64.
// int32 pairs misread as int64 give values ~ (hi*2^32 + lo) >> n, far outside [0,N).
__global__ void k_detect(const void* ei_raw, int E, int n) {
    if (threadIdx.x == 0 && blockIdx.x == 0) {
        const long long* p = (const long long*)ei_raw;
        int bad = 0;
        int samples = E < 512 ? E : 512;
        for (int i = 0; i < samples; i++) {
            long long v = p[i];
            if (v < 0 || v >= n) { bad = 1; break; }
        }
        g_i64mode = bad ? 0 : 1;
    }
}

__device__ __forceinline__ int edge_at(const void* ei_raw, size_t idx) {
    if (g_i64mode) return (int)((const long long*)ei_raw)[idx];
    return ((const int*)ei_raw)[idx];
}

// ---------------- small elementwise / graph kernels ----------------
__global__ void k_init_deg(int n) {
    int i = blockIdx.x * blockDim.x + threadIdx.x;
    if (i < n) g_deg[i] = 1.0f;  // self-loop
}

__global__ void k_deg(const void* __restrict__ ei, int E, int n) {
    int i = blockIdx.x * blockDim.x + threadIdx.x;
    if (i < E) {
        int t = edge_at(ei, (size_t)E + i);
        t = max(0, min(n - 1, t));
        atomicAdd(&g_deg[t], 1.0f);  // in-degree over targets
    }
}

__global__ void k_dinv(int n) {
    int i = blockIdx.x * blockDim.x + threadIdx.x;
    if (i < n) g_deg[i] = rsqrtf(g_deg[i]);  // deg >= 1 always
}

// initialize agg with the self-loop contribution: agg[i,:] = xw[i,:] * dinv[i]^2
__global__ void k_self(int total) {
    int i = blockIdx.x * blockDim.x + threadIdx.x;
    if (i < total) {
        float d = g_deg[i >> 7];
        g_agg[i] = g_xw[i] * (d * d);
    }
}

// one warp per edge: agg[col,:] += xw[row,:] * dinv[row]*dinv[col]
__global__ void k_scatter(const void* __restrict__ ei, int E, int n) {
    int gw = (blockIdx.x * blockDim.x + threadIdx.x) >> 5;
    int lane = threadIdx.x & 31;
    if (gw >= E) return;
    int r = edge_at(ei, gw);
    int c = edge_at(ei, (size_t)E + gw);
    r = max(0, min(n - 1, r));
    c = max(0, min(n - 1, c));
    float w = g_deg[r] * g_deg[c];
    const float* src = g_xw  + (size_t)r * G_CH;
    float*       dst = g_agg + (size_t)c * G_CH;
#pragma unroll
    for (int i = 0; i < G_CH / 32; i++) {
        atomicAdd(&dst[lane + 32 * i], src[lane + 32 * i] * w);
    }
}

// x1 = relu(agg + b_gcn) in place
__global__ void k_bias_relu(const float* __restrict__ b, int total) {
    int i = blockIdx.x * blockDim.x + threadIdx.x;
    if (i < total) {
        float v = g_agg[i] + b[i & (G_CH - 1)];
        g_agg[i] = fmaxf(v, 0.0f);
    }
}

// ---------------- tiled fp32 GEMM: C = act( [A1|A2] @ B + bias ) ----------------
//   A2_MODE: 0 = none, 1 = g_agg (concat second operand)
//   C_MODE:  0 = runtime pointer Cp, 1 = g_xw
template<int BM, int BN, int BK, int TM, int TN, bool HAS_BIAS, bool RELU,
         int A2_MODE, int C_MODE>
__global__ void __launch_bounds__((BM / TM) * (BN / TN))
gemm_kernel(const float* __restrict__ A1, int K1, int K2,
            const float* __restrict__ Bm,
            const float* __restrict__ bias,
            float* __restrict__ Cp, int M, int N)
{
    constexpr int THREADS = (BM / TM) * (BN / TN);
    __shared__ __align__(16) float As[BK][BM + 4];
    __shared__ __align__(16) float Bs[BK][BN + 4];

    const int tid  = threadIdx.x;
    const int tcol = tid % (BN / TN);
    const int trow = tid / (BN / TN);
    const int m0 = blockIdx.x * BM;
    const int n0 = blockIdx.y * BN;
    const int K = K1 + K2;

    float acc[TM][TN];
#pragma unroll
    for (int i = 0; i < TM; i++)
#pragma unroll
        for (int j = 0; j < TN; j++) acc[i][j] = 0.0f;

    constexpr int A_ITERS = (BM * BK) / THREADS;
    constexpr int B_ITERS = (BK * BN) / THREADS;

    for (int k0 = 0; k0 < K; k0 += BK) {
#pragma unroll
        for (int it = 0; it < A_ITERS; it++) {
            int idx = tid + it * THREADS;
            int r = idx / BK, c = idx % BK;
            int gm = m0 + r, gk = k0 + c;
            float v = 0.0f;
            if (gm < M) {
                if (gk < K1) v = __ldg(&A1[(size_t)gm * K1 + gk]);
                else if (A2_MODE == 1) v = g_agg[(size_t)gm * K2 + (gk - K1)];
            }
            As[c][r] = v;
        }
#pragma unroll
        for (int it = 0; it < B_ITERS; it++) {
            int idx = tid + it * THREADS;
            int r = idx / BN, c = idx % BN;
            int gn = n0 + c;
            Bs[r][c] = (gn < N) ? __ldg(&Bm[(size_t)(k0 + r) * N + gn]) : 0.0f;
        }
        __syncthreads();

#pragma unroll
        for (int k = 0; k < BK; k++) {
            float ra[TM], rb[TN];
            const float4* pa = reinterpret_cast<const float4*>(&As[k][trow * TM]);
#pragma unroll
            for (int i = 0; i < TM / 4; i++) {
                float4 t = pa[i];
                ra[4 * i + 0] = t.x; ra[4 * i + 1] = t.y;
                ra[4 * i + 2] = t.z; ra[4 * i + 3] = t.w;
            }
            const float4* pb = reinterpret_cast<const float4*>(&Bs[k][tcol * TN]);
#pragma unroll
            for (int j = 0; j < TN / 4; j++) {
                float4 t = pb[j];
                rb[4 * j + 0] = t.x; rb[4 * j + 1] = t.y;
                rb[4 * j + 2] = t.z; rb[4 * j + 3] = t.w;
            }
#pragma unroll
            for (int i = 0; i < TM; i++)
#pragma unroll
                for (int j = 0; j < TN; j++)
                    acc[i][j] = fmaf(ra[i], rb[j], acc[i][j]);
        }
        __syncthreads();
    }

#pragma unroll
    for (int i = 0; i < TM; i++) {
        int gm = m0 + trow * TM + i;
        if (gm >= M) continue;
#pragma unroll
        for (int j = 0; j < TN; j++) {
            int gn = n0 + tcol * TN + j;
            if (gn < N) {
                float v = acc[i][j];
                if (HAS_BIAS) v += bias[gn];
                if (RELU) v = fmaxf(v, 0.0f);
                if (C_MODE == 1) g_xw[(size_t)gm * N + gn] = v;
                else             Cp[(size_t)gm * N + gn] = v;
            }
        }
    }
}

// ---------------- launch ----------------
extern "C" void kernel_launch(void* const* d_in, const int* in_sizes, int n_in,
                              void* d_out, int out_size) {
    // Identify inputs by element count (do NOT trust positional order).
    const float* x     = nullptr;  int x_cnt = 0;
    const void*  ei    = nullptr;  int ei_cnt = 0;
    const float* W_gcn = nullptr;
    const float* b_gcn = nullptr;
    const float* W_hid = nullptr;
    const float* b_hid = nullptr;
    const float* W_cls = nullptr;
    const float* b_cls = nullptr;

    int max_cnt = 0;
    for (int i = 0; i < n_in; i++) if (in_sizes[i] > max_cnt) max_cnt = in_sizes[i];
    for (int i = 0; i < n_in; i++) {
        int c = in_sizes[i];
        if      (c == IN_CH * G_CH)            W_gcn = (const float*)d_in[i];
        else if (c == (IN_CH + G_CH) * HID)    W_hid = (const float*)d_in[i];
        else if (c == HID * NCLS)              W_cls = (const float*)d_in[i];
        else if (c == G_CH)                    b_gcn = (const float*)d_in[i];
        else if (c == HID)                     b_hid = (const float*)d_in[i];
        else if (c == NCLS)                    b_cls = (const float*)d_in[i];
        else if (c == max_cnt && c % IN_CH == 0) { x = (const float*)d_in[i]; x_cnt = c; }
    }
    const int N = x_cnt / IN_CH;

    // edge_index: among remaining inputs, the one whose count != 2*N (img_sizes is [N,2]).
    for (int i = 0; i < n_in; i++) {
        const void* p = d_in[i];
        if (p == (const void*)x || p == (const void*)W_gcn || p == (const void*)W_hid ||
            p == (const void*)W_cls || p == (const void*)b_gcn || p == (const void*)b_hid ||
            p == (const void*)b_cls) continue;
        int c = in_sizes[i];
        if (c != 2 * N) { ei = p; ei_cnt = c; }
        else if (ei == nullptr) { ei = p; ei_cnt = c; }
    }
    const int E = ei_cnt / 2;

    float* h      = (float*)d_out;                 // [N, 512]
    float* logits = h + (size_t)N * HID;           // [N, 79]

    const int mblocks = (N + 127) / 128;

    // 0) probe edge_index dtype (int64 vs int32)
    k_detect<<<1, 32>>>(ei, E, N);

    // 1) xw = x @ W_gcn  -> g_xw
    gemm_kernel<128, 128, 16, 8, 4, false, false, 0, 1>
        <<<dim3(mblocks, 1), 512>>>(x, IN_CH, 0, W_gcn, nullptr, nullptr, N, G_CH);

    // 2) degree (with self-loops), then dinv
    k_init_deg<<<(N + 255) / 256, 256>>>(N);
    k_deg<<<(E + 255) / 256, 256>>>(ei, E, N);
    k_dinv<<<(N + 255) / 256, 256>>>(N);

    // 3) agg = self-loop term, then scatter edges, then bias+relu -> x1 (in g_agg)
    int tot = N * G_CH;
    k_self<<<(tot + 255) / 256, 256>>>(tot);
    k_scatter<<<(E + 7) / 8, 256>>>(ei, E, N);
    k_bias_relu<<<(tot + 255) / 256, 256>>>(b_gcn, tot);

    // 4) h = relu([x | g_agg] @ W_hid + b_hid) -> d_out
    gemm_kernel<128, 128, 16, 8, 4, true, true, 1, 0>
        <<<dim3(mblocks, HID / 128), 512>>>(x, IN_CH, G_CH, W_hid, b_hid, h, N, HID);

    // 5) logits = h @ W_cls + b_cls
    gemm_kernel<128, 128, 16, 8, 4, true, false, 0, 0>
        <<<dim3(mblocks, 1), 512>>>(h, HID, 0, W_cls, b_cls, logits, N, NCLS);
}

// round 7
// speedup vs baseline: 1.6700x; 1.6700x over previous
#include <cuda_runtime.h>
#include <cuda_bf16.h>
#include <cstdint>

#define N_NODES 100000
#define IN_CH   1280
#define G_CH    128
#define HID     512
#define NCLS    79

// ---------------- scratch (device globals: no allocation allowed) ----------------
__device__ float g_xw [(size_t)N_NODES * G_CH];   // x @ W_gcn
__device__ float g_agg[(size_t)N_NODES * G_CH];   // aggregated messages -> x1
__device__ float g_deg[N_NODES];                  // degree -> dinv (in place)
__device__ int   g_i64mode;                       // 1 if edge_index is int64, else int32

// ---------------- warp-mma helpers (plain PTX, valid on sm_103 non-a) ----------------
__device__ __forceinline__ uint32_t smem_u32(const void* p) {
    uint32_t a;
    asm("{ .reg .u64 t; cvta.to.shared.u64 t, %1; cvt.u32.u64 %0, t; }" : "=r"(a) : "l"(p));
    return a;
}
__device__ __forceinline__ void ldm_x4(uint32_t* r, uint32_t addr) {
    asm volatile("ldmatrix.sync.aligned.m8n8.x4.shared.b16 {%0,%1,%2,%3}, [%4];"
        : "=r"(r[0]), "=r"(r[1]), "=r"(r[2]), "=r"(r[3]) : "r"(addr));
}
__device__ __forceinline__ void mma16816(float* c, const uint32_t* a, const uint32_t* b) {
    asm volatile("mma.sync.aligned.m16n8k16.row.col.f32.bf16.bf16.f32 "
        "{%0,%1,%2,%3}, {%4,%5,%6,%7}, {%8,%9}, {%0,%1,%2,%3};"
        : "+f"(c[0]), "+f"(c[1]), "+f"(c[2]), "+f"(c[3])
        : "r"(a[0]), "r"(a[1]), "r"(a[2]), "r"(a[3]), "r"(b[0]), "r"(b[1]));
}

// ---------------- split-bf16 tensor-core GEMM ----------------
// C = act([A1 | g_agg] @ B + bias).  BM=128, BN=128, BK=32. 8 warps (2m x 4n),
// warp tile 64x32. Split: D = Ah*Bh + Ah*Bl + Al*Bh (lo*lo dropped).
// A2M: 0 none, 1 concat g_agg.  CM: 0 -> Cp, 1 -> g_xw.
#define RS 40   // smem row stride in bf16 elems (32 + 8 pad) -> conflict-free ldmatrix

template<int A2M, int CM, bool BIAS, bool RELU>
__global__ void __launch_bounds__(256, 2)
tc_gemm(const float* __restrict__ A1, int K1, int K2,
        const float* __restrict__ Bm, const float* __restrict__ bias,
        float* __restrict__ Cp, int M, int NB, int Nout)
{
    __shared__ __align__(16) __nv_bfloat16 sAh[128 * RS];
    __shared__ __align__(16) __nv_bfloat16 sAl[128 * RS];
    __shared__ __align__(16) __nv_bfloat16 sBh[128 * RS];
    __shared__ __align__(16) __nv_bfloat16 sBl[128 * RS];

    const int tid  = threadIdx.x;
    const int wid  = tid >> 5;
    const int lane = tid & 31;
    const int wm = wid >> 2;          // 0..1  (m offset wm*64)
    const int wn = wid & 3;           // 0..3  (n offset wn*32)
    const int m0 = blockIdx.x * 128;
    const int n0 = blockIdx.y * 128;

    const uint32_t uAh = smem_u32(sAh), uAl = smem_u32(sAl);
    const uint32_t uBh = smem_u32(sBh), uBl = smem_u32(sBl);

    float acc[4][4][4];
#pragma unroll
    for (int i = 0; i < 4; i++)
#pragma unroll
        for (int j = 0; j < 4; j++)
#pragma unroll
            for (int r = 0; r < 4; r++) acc[i][j][r] = 0.0f;

    const int K = K1 + K2;
    const int nchunks = K >> 5;
    const bool b_vec_ok = (NB & 3) == 0;   // uniform: float4 legal for B rows

    // ldmatrix row/col assignment (same formula for A and B tiles):
    const int lrow = lane & 15;         // row within 16-row group
    const int lko  = (lane >> 4) << 3;  // k offset 0 or 8

    for (int ch = 0; ch < nchunks; ch++) {
        const int k0 = ch << 5;

        // ---- load A chunk 128x32 fp32, split into hi/lo bf16 ----
        // 1024 float4 / 256 threads = 4 each; row = idx/8, kq = idx%8 (k = kq*4)
#pragma unroll
        for (int it = 0; it < 4; it++) {
            int idx = tid + it * 256;
            int row = idx >> 3, kq = idx & 7;
            int gm = m0 + row, gk = k0 + kq * 4;
            float4 v = make_float4(0.f, 0.f, 0.f, 0.f);
            if (gm < M) {
                if (gk < K1) v = *reinterpret_cast<const float4*>(&A1[(size_t)gm * K1 + gk]);
                else if (A2M == 1) v = *reinterpret_cast<const float4*>(&g_agg[(size_t)gm * (size_t)K2 + (gk - K1)]);
            }
            __nv_bfloat16 h0 = __float2bfloat16(v.x), h1 = __float2bfloat16(v.y);
            __nv_bfloat16 h2 = __float2bfloat16(v.z), h3 = __float2bfloat16(v.w);
            __nv_bfloat16 l0 = __float2bfloat16(v.x - __bfloat162float(h0));
            __nv_bfloat16 l1 = __float2bfloat16(v.y - __bfloat162float(h1));
            __nv_bfloat16 l2 = __float2bfloat16(v.z - __bfloat162float(h2));
            __nv_bfloat16 l3 = __float2bfloat16(v.w - __bfloat162float(h3));
            int so = row * RS + kq * 4;
            __nv_bfloat162* ph = reinterpret_cast<__nv_bfloat162*>(&sAh[so]);
            ph[0] = __nv_bfloat162(h0, h1); ph[1] = __nv_bfloat162(h2, h3);
            __nv_bfloat162* pl = reinterpret_cast<__nv_bfloat162*>(&sAl[so]);
            pl[0] = __nv_bfloat162(l0, l1); pl[1] = __nv_bfloat162(l2, l3);
        }
        // ---- load B chunk 32 x 128 fp32 (gmem [k][n]) -> smem [n][k] hi/lo ----
        // idx over 1024 float4: kk = idx/32 (0..31), nq = idx%32 (n = nq*4)
#pragma unroll
        for (int it = 0; it < 4; it++) {
            int idx = tid + it * 256;
            int kk = idx >> 5, nq = idx & 31;
            int gk = k0 + kk, gn = n0 + nq * 4;
            float4 v = make_float4(0.f, 0.f, 0.f, 0.f);
            if (b_vec_ok && gn + 3 < NB) {
                v = *reinterpret_cast<const float4*>(&Bm[(size_t)gk * NB + gn]);
            } else {
                const float* p = &Bm[(size_t)gk * NB];
                if (gn     < NB) v.x = p[gn];
                if (gn + 1 < NB) v.y = p[gn + 1];
                if (gn + 2 < NB) v.z = p[gn + 2];
                if (gn + 3 < NB) v.w = p[gn + 3];
            }
            float vv[4] = {v.x, v.y, v.z, v.w};
#pragma unroll
            for (int j = 0; j < 4; j++) {
                __nv_bfloat16 hb = __float2bfloat16(vv[j]);
                __nv_bfloat16 lb = __float2bfloat16(vv[j] - __bfloat162float(hb));
                int so = (nq * 4 + j) * RS + kk;
                sBh[so] = hb;
                sBl[so] = lb;
            }
        }
        __syncthreads();

        // ---- compute: 2 k16 steps ----
#pragma unroll
        for (int s = 0; s < 2; s++) {
            const int ks = s * 16 + lko;
            uint32_t bh[4][2], bl[4][2];
#pragma unroll
            for (int g = 0; g < 2; g++) {   // two n16 groups -> 4 n8 tiles
                uint32_t r[4];
                uint32_t addr = uBh + ((wn * 32 + g * 16 + lrow) * RS + ks) * 2;
                ldm_x4(r, addr);
                bh[2 * g][0] = r[0]; bh[2 * g][1] = r[2];
                bh[2 * g + 1][0] = r[1]; bh[2 * g + 1][1] = r[3];
                addr = uBl + ((wn * 32 + g * 16 + lrow) * RS + ks) * 2;
                ldm_x4(r, addr);
                bl[2 * g][0] = r[0]; bl[2 * g][1] = r[2];
                bl[2 * g + 1][0] = r[1]; bl[2 * g + 1][1] = r[3];
            }
            uint32_t ah[4][4], al[4][4];
#pragma unroll
            for (int mt = 0; mt < 4; mt++) {
                uint32_t addr = uAh + ((wm * 64 + mt * 16 + lrow) * RS + ks) * 2;
                ldm_x4(ah[mt], addr);
                addr = uAl + ((wm * 64 + mt * 16 + lrow) * RS + ks) * 2;
                ldm_x4(al[mt], addr);
            }
#pragma unroll
            for (int mt = 0; mt < 4; mt++)
#pragma unroll
                for (int nt = 0; nt < 4; nt++) {
                    mma16816(acc[mt][nt], ah[mt], bh[nt]);
                    mma16816(acc[mt][nt], ah[mt], bl[nt]);
                    mma16816(acc[mt][nt], al[mt], bh[nt]);
                }
        }
        __syncthreads();
    }

    // ---- epilogue ----
    const int qr = lane >> 2;        // 0..7
    const int qc = (lane & 3) * 2;   // 0,2,4,6
#pragma unroll
    for (int mt = 0; mt < 4; mt++) {
#pragma unroll
        for (int nt = 0; nt < 4; nt++) {
#pragma unroll
            for (int half = 0; half < 2; half++) {
                int gm = m0 + wm * 64 + mt * 16 + qr + half * 8;
                if (gm >= M) continue;
#pragma unroll
                for (int j = 0; j < 2; j++) {
                    int gn = n0 + wn * 32 + nt * 8 + qc + j;
                    if (gn >= Nout) continue;
                    float v = acc[mt][nt][half * 2 + j];
                    if (BIAS) v += __ldg(&bias[gn]);
                    if (RELU) v = fmaxf(v, 0.0f);
                    if (CM == 1) g_xw[(size_t)gm * Nout + gn] = v;
                    else         Cp[(size_t)gm * Nout + gn] = v;
                }
            }
        }
    }
}

// ---------------- edge dtype probe ----------------
__global__ void k_detect(const void* ei_raw, int E, int n) {
    if (threadIdx.x == 0 && blockIdx.x == 0) {
        const long long* p = (const long long*)ei_raw;
        int bad = 0;
        int samples = E < 512 ? E : 512;
        for (int i = 0; i < samples; i++) {
            long long v = p[i];
            if (v < 0 || v >= n) { bad = 1; break; }
        }
        g_i64mode = bad ? 0 : 1;
    }
}
__device__ __forceinline__ int edge_at(const void* ei_raw, size_t idx) {
    if (g_i64mode) return (int)((const long long*)ei_raw)[idx];
    return ((const int*)ei_raw)[idx];
}

// ---------------- graph / elementwise kernels ----------------
__global__ void k_init_deg(int n) {
    int i = blockIdx.x * blockDim.x + threadIdx.x;
    if (i < n) g_deg[i] = 1.0f;
}
__global__ void k_deg(const void* __restrict__ ei, int E, int n) {
    int i = blockIdx.x * blockDim.x + threadIdx.x;
    if (i < E) {
        int t = edge_at(ei, (size_t)E + i);
        t = max(0, min(n - 1, t));
        atomicAdd(&g_deg[t], 1.0f);
    }
}
__global__ void k_dinv(int n) {
    int i = blockIdx.x * blockDim.x + threadIdx.x;
    if (i < n) g_deg[i] = rsqrtf(g_deg[i]);
}
__global__ void k_self(int total) {
    int i = blockIdx.x * blockDim.x + threadIdx.x;
    if (i < total) {
        float d = g_deg[i >> 7];
        g_agg[i] = g_xw[i] * (d * d);
    }
}
__global__ void k_scatter(const void* __restrict__ ei, int E, int n) {
    int gw = (blockIdx.x * blockDim.x + threadIdx.x) >> 5;
    int lane = threadIdx.x & 31;
    if (gw >= E) return;
    int r = edge_at(ei, gw);
    int c = edge_at(ei, (size_t)E + gw);
    r = max(0, min(n - 1, r));
    c = max(0, min(n - 1, c));
    float w = g_deg[r] * g_deg[c];
    const float* src = g_xw  + (size_t)r * G_CH;
    float*       dst = g_agg + (size_t)c * G_CH;
#pragma unroll
    for (int i = 0; i < G_CH / 32; i++)
        atomicAdd(&dst[lane + 32 * i], src[lane + 32 * i] * w);
}
__global__ void k_bias_relu(const float* __restrict__ b, int total) {
    int i = blockIdx.x * blockDim.x + threadIdx.x;
    if (i < total) {
        float v = g_agg[i] + b[i & (G_CH - 1)];
        g_agg[i] = fmaxf(v, 0.0f);
    }
}

// ---------------- launch ----------------
extern "C" void kernel_launch(void* const* d_in, const int* in_sizes, int n_in,
                              void* d_out, int out_size) {
    const float* x     = nullptr;  int x_cnt = 0;
    const void*  ei    = nullptr;  int ei_cnt = 0;
    const float* W_gcn = nullptr;
    const float* b_gcn = nullptr;
    const float* W_hid = nullptr;
    const float* b_hid = nullptr;
    const float* W_cls = nullptr;
    const float* b_cls = nullptr;

    int max_cnt = 0;
    for (int i = 0; i < n_in; i++) if (in_sizes[i] > max_cnt) max_cnt = in_sizes[i];
    for (int i = 0; i < n_in; i++) {
        int c = in_sizes[i];
        if      (c == IN_CH * G_CH)            W_gcn = (const float*)d_in[i];
        else if (c == (IN_CH + G_CH) * HID)    W_hid = (const float*)d_in[i];
        else if (c == HID * NCLS)              W_cls = (const float*)d_in[i];
        else if (c == G_CH)                    b_gcn = (const float*)d_in[i];
        else if (c == HID)                     b_hid = (const float*)d_in[i];
        else if (c == NCLS)                    b_cls = (const float*)d_in[i];
        else if (c == max_cnt && c % IN_CH == 0) { x = (const float*)d_in[i]; x_cnt = c; }
    }
    const int N = x_cnt / IN_CH;

    for (int i = 0; i < n_in; i++) {
        const void* p = d_in[i];
        if (p == (const void*)x || p == (const void*)W_gcn || p == (const void*)W_hid ||
            p == (const void*)W_cls || p == (const void*)b_gcn || p == (const void*)b_hid ||
            p == (const void*)b_cls) continue;
        int c = in_sizes[i];
        if (c != 2 * N) { ei = p; ei_cnt = c; }
        else if (ei == nullptr) { ei = p; ei_cnt = c; }
    }
    const int E = ei_cnt / 2;

    float* h      = (float*)d_out;                 // [N, 512]
    float* logits = h + (size_t)N * HID;           // [N, 79]

    const int mblocks = (N + 127) / 128;

    // 0) probe edge_index dtype
    k_detect<<<1, 32>>>(ei, E, N);

    // 1) xw = x @ W_gcn -> g_xw
    tc_gemm<0, 1, false, false><<<dim3(mblocks, 1), 256>>>(
        x, IN_CH, 0, W_gcn, nullptr, nullptr, N, G_CH, G_CH);

    // 2) degree + dinv
    k_init_deg<<<(N + 255) / 256, 256>>>(N);
    k_deg<<<(E + 255) / 256, 256>>>(ei, E, N);
    k_dinv<<<(N + 255) / 256, 256>>>(N);

    // 3) aggregation -> x1 in g_agg
    int tot = N * G_CH;
    k_self<<<(tot + 255) / 256, 256>>>(tot);
    k_scatter<<<(E + 7) / 8, 256>>>(ei, E, N);
    k_bias_relu<<<(tot + 255) / 256, 256>>>(b_gcn, tot);

    // 4) h = relu([x | x1] @ W_hid + b_hid) -> d_out
    tc_gemm<1, 0, true, true><<<dim3(mblocks, 4), 256>>>(
        x, IN_CH, G_CH, W_hid, b_hid, h, N, HID, HID);

    // 5) logits = h @ W_cls + b_cls
    tc_gemm<0, 0, true, false><<<dim3(mblocks, 1), 256>>>(
        h, HID, 0, W_cls, b_cls, logits, N, NCLS, NCLS);
}

// round 8
// speedup vs baseline: 3.5853x; 2.1469x over previous
#include <cuda_runtime.h>
#include <cuda_bf16.h>
#include <cstdint>

#define N_NODES 100000
#define N_PAD   100096
#define IN_CH   1280
#define G_CH    128
#define HID     512
#define NCLS    79
#define KCAT    (IN_CH + G_CH)

// ---------------- scratch (device globals; zero-init; no allocation allowed) ----------------
__device__ float g_xw [(size_t)N_PAD * G_CH];     // x @ W_gcn (fp32, for scatter)
__device__ float g_agg[(size_t)N_PAD * G_CH];     // aggregated messages
__device__ float g_deg[N_NODES];
__device__ int   g_i64mode;

// split-bf16 planes
__device__ __nv_bfloat16 g_xh [(size_t)N_PAD * IN_CH];
__device__ __nv_bfloat16 g_xl [(size_t)N_PAD * IN_CH];
__device__ __nv_bfloat16 g_x1h[(size_t)N_PAD * G_CH];
__device__ __nv_bfloat16 g_x1l[(size_t)N_PAD * G_CH];
__device__ __nv_bfloat16 g_hh [(size_t)N_PAD * HID];
__device__ __nv_bfloat16 g_hl [(size_t)N_PAD * HID];
// weights transposed to [n][k], k-contiguous; W_cls n padded to 128
__device__ __nv_bfloat16 g_wgh[G_CH * IN_CH],  g_wgl[G_CH * IN_CH];
__device__ __nv_bfloat16 g_whh[HID * KCAT],    g_whl[HID * KCAT];
__device__ __nv_bfloat16 g_wch[128 * HID],     g_wcl[128 * HID];

// ---------------- PTX helpers ----------------
__device__ __forceinline__ uint32_t smem_u32(const void* p) {
    uint32_t a;
    asm("{ .reg .u64 t; cvta.to.shared.u64 t, %1; cvt.u32.u64 %0, t; }" : "=r"(a) : "l"(p));
    return a;
}
__device__ __forceinline__ void cp16(uint32_t dst, const void* src) {
    asm volatile("cp.async.cg.shared.global [%0], [%1], 16;" :: "r"(dst), "l"(src));
}
__device__ __forceinline__ void ldm_x4(uint32_t* r, uint32_t addr) {
    asm volatile("ldmatrix.sync.aligned.m8n8.x4.shared.b16 {%0,%1,%2,%3}, [%4];"
        : "=r"(r[0]), "=r"(r[1]), "=r"(r[2]), "=r"(r[3]) : "r"(addr));
}
__device__ __forceinline__ void mma16816(float* c, const uint32_t* a, const uint32_t* b) {
    asm volatile("mma.sync.aligned.m16n8k16.row.col.f32.bf16.bf16.f32 "
        "{%0,%1,%2,%3}, {%4,%5,%6,%7}, {%8,%9}, {%0,%1,%2,%3};"
        : "+f"(c[0]), "+f"(c[1]), "+f"(c[2]), "+f"(c[3])
        : "r"(a[0]), "r"(a[1]), "r"(a[2]), "r"(a[3]), "r"(b[0]), "r"(b[1]));
}
__device__ __forceinline__ void split2(float v, __nv_bfloat16& h, __nv_bfloat16& l) {
    h = __float2bfloat16(v);
    l = __float2bfloat16(v - __bfloat162float(h));
}

// ---------------- split preprocessing ----------------
__global__ void k_split_x(const float4* __restrict__ x4, size_t total4) {
    size_t i = (size_t)blockIdx.x * blockDim.x + threadIdx.x;
    if (i >= total4) return;
    float4 v = x4[i];
    __nv_bfloat16 h0, h1, h2, h3, l0, l1, l2, l3;
    split2(v.x, h0, l0); split2(v.y, h1, l1); split2(v.z, h2, l2); split2(v.w, h3, l3);
    __nv_bfloat162* ph = reinterpret_cast<__nv_bfloat162*>(&g_xh[i * 4]);
    ph[0] = __nv_bfloat162(h0, h1); ph[1] = __nv_bfloat162(h2, h3);
    __nv_bfloat162* pl = reinterpret_cast<__nv_bfloat162*>(&g_xl[i * 4]);
    pl[0] = __nv_bfloat162(l0, l1); pl[1] = __nv_bfloat162(l2, l3);
}

// WMODE 0: W_gcn [1280][128] -> g_wg* [128][1280]
// WMODE 1: W_hid [1408][512] -> g_wh* [512][1408]
// WMODE 2: W_cls [512][79]   -> g_wc* [128][512] (rows 79..127 zero)
template<int WMODE>
__global__ void k_split_w(const float* __restrict__ W) {
    constexpr int KD   = (WMODE == 0) ? IN_CH : (WMODE == 1) ? KCAT : HID;
    constexpr int ND   = (WMODE == 0) ? G_CH  : (WMODE == 1) ? HID  : NCLS;
    constexpr int NPAD = (WMODE == 0) ? G_CH  : (WMODE == 1) ? HID  : 128;
    int idx = blockIdx.x * blockDim.x + threadIdx.x;
    if (idx >= NPAD * KD) return;
    int n = idx / KD, k = idx % KD;
    float v = (n < ND) ? __ldg(&W[(size_t)k * ND + n]) : 0.0f;
    __nv_bfloat16 h, l; split2(v, h, l);
    if (WMODE == 0) { g_wgh[idx] = h; g_wgl[idx] = l; }
    if (WMODE == 1) { g_whh[idx] = h; g_whl[idx] = l; }
    if (WMODE == 2) { g_wch[idx] = h; g_wcl[idx] = l; }
}

// ---------------- split-bf16 tensor-core GEMM (pre-split operands, cp.async) ----------------
// AM: 0 = x planes (K=1280), 1 = [x | x1] (K=1408), 2 = h planes (K=512)
// BMODE: 0 = W_gcn planes, 1 = W_hid, 2 = W_cls
// CM: 0 -> Cp fp32, 1 -> g_xw fp32.  HSPLIT: also write g_hh/g_hl.
#define RS 40   // smem row stride in bf16 (32 data + 8 pad); LDSM conflict-free

template<int AM, int BMODE, bool BIAS, bool RELU, bool HSPLIT, int CM>
__global__ void __launch_bounds__(256, 2)
tc_gemm(const float* __restrict__ bias, float* __restrict__ Cp, int M, int Nout)
{
    __shared__ __align__(16) __nv_bfloat16 sAh[128 * RS];
    __shared__ __align__(16) __nv_bfloat16 sAl[128 * RS];
    __shared__ __align__(16) __nv_bfloat16 sBh[128 * RS];
    __shared__ __align__(16) __nv_bfloat16 sBl[128 * RS];

    const int tid  = threadIdx.x;
    const int wid  = tid >> 5;
    const int lane = tid & 31;
    const int wm = wid >> 2;
    const int wn = wid & 3;
    const int m0 = blockIdx.x * 128;
    const int n0 = blockIdx.y * 128;

    const uint32_t uAh = smem_u32(sAh), uAl = smem_u32(sAl);
    const uint32_t uBh = smem_u32(sBh), uBl = smem_u32(sBl);

    float acc[4][4][4];
#pragma unroll
    for (int i = 0; i < 4; i++)
#pragma unroll
        for (int j = 0; j < 4; j++)
#pragma unroll
            for (int r = 0; r < 4; r++) acc[i][j][r] = 0.0f;

    constexpr int K  = (AM == 0) ? IN_CH : (AM == 1) ? KCAT : HID;
    constexpr int Kb = (BMODE == 0) ? IN_CH : (BMODE == 1) ? KCAT : HID;
    constexpr int nchunks = K >> 5;

    const int lrow = lane & 15;
    const int lko  = (lane >> 4) << 3;

    for (int ch = 0; ch < nchunks; ch++) {
        const int k0 = ch << 5;

        // resolve A source (uniform per chunk)
        const __nv_bfloat16 *pAh, *pAl; int Kd, koff;
        if (AM == 0) { pAh = g_xh; pAl = g_xl; Kd = IN_CH; koff = k0; }
        else if (AM == 2) { pAh = g_hh; pAl = g_hl; Kd = HID; koff = k0; }
        else {
            if (k0 < IN_CH) { pAh = g_xh;  pAl = g_xl;  Kd = IN_CH; koff = k0; }
            else            { pAh = g_x1h; pAl = g_x1l; Kd = G_CH;  koff = k0 - IN_CH; }
        }
        const __nv_bfloat16 *pBh, *pBl;
        if (BMODE == 0) { pBh = g_wgh; pBl = g_wgl; }
        else if (BMODE == 1) { pBh = g_whh; pBl = g_whl; }
        else { pBh = g_wch; pBl = g_wcl; }

        // 512 x 16B per plane; 256 threads x 2 iters
#pragma unroll
        for (int it = 0; it < 2; it++) {
            int o = tid + it * 256;
            int row = o >> 2, grp = o & 3;
            uint32_t so = (uint32_t)(row * (RS * 2) + grp * 16);
            size_t aoff = (size_t)(m0 + row) * Kd + koff + grp * 8;
            cp16(uAh + so, pAh + aoff);
            cp16(uAl + so, pAl + aoff);
            size_t boff = (size_t)(n0 + row) * Kb + k0 + grp * 8;
            cp16(uBh + so, pBh + boff);
            cp16(uBl + so, pBl + boff);
        }
        asm volatile("cp.async.commit_group;");
        asm volatile("cp.async.wait_group 0;");
        __syncthreads();

        // compute: 2 k16 steps
#pragma unroll
        for (int s = 0; s < 2; s++) {
            const int ks = s * 16 + lko;
            uint32_t bh[4][2], bl[4][2];
#pragma unroll
            for (int g = 0; g < 2; g++) {
                uint32_t r[4];
                uint32_t addr = uBh + ((wn * 32 + g * 16 + lrow) * RS + ks) * 2;
                ldm_x4(r, addr);
                bh[2 * g][0] = r[0]; bh[2 * g][1] = r[2];
                bh[2 * g + 1][0] = r[1]; bh[2 * g + 1][1] = r[3];
                addr = uBl + ((wn * 32 + g * 16 + lrow) * RS + ks) * 2;
                ldm_x4(r, addr);
                bl[2 * g][0] = r[0]; bl[2 * g][1] = r[2];
                bl[2 * g + 1][0] = r[1]; bl[2 * g + 1][1] = r[3];
            }
            uint32_t ah[4][4], al[4][4];
#pragma unroll
            for (int mt = 0; mt < 4; mt++) {
                uint32_t addr = uAh + ((wm * 64 + mt * 16 + lrow) * RS + ks) * 2;
                ldm_x4(ah[mt], addr);
                addr = uAl + ((wm * 64 + mt * 16 + lrow) * RS + ks) * 2;
                ldm_x4(al[mt], addr);
            }
#pragma unroll
            for (int mt = 0; mt < 4; mt++)
#pragma unroll
                for (int nt = 0; nt < 4; nt++) {
                    mma16816(acc[mt][nt], ah[mt], bh[nt]);
                    mma16816(acc[mt][nt], ah[mt], bl[nt]);
                    mma16816(acc[mt][nt], al[mt], bh[nt]);
                }
        }
        __syncthreads();
    }

    // ---- epilogue ----
    const int qr = lane >> 2;
    const int qc = (lane & 3) * 2;
#pragma unroll
    for (int mt = 0; mt < 4; mt++) {
#pragma unroll
        for (int nt = 0; nt < 4; nt++) {
#pragma unroll
            for (int half = 0; half < 2; half++) {
                int gm = m0 + wm * 64 + mt * 16 + qr + half * 8;
                if (gm >= M) continue;
#pragma unroll
                for (int j = 0; j < 2; j++) {
                    int gn = n0 + wn * 32 + nt * 8 + qc + j;
                    if (gn >= Nout) continue;
                    float v = acc[mt][nt][half * 2 + j];
                    if (BIAS) v += __ldg(&bias[gn]);
                    if (RELU) v = fmaxf(v, 0.0f);
                    if (CM == 1) g_xw[(size_t)gm * Nout + gn] = v;
                    else         Cp[(size_t)gm * Nout + gn] = v;
                    if (HSPLIT) {
                        __nv_bfloat16 hb, lb; split2(v, hb, lb);
                        g_hh[(size_t)gm * HID + gn] = hb;
                        g_hl[(size_t)gm * HID + gn] = lb;
                    }
                }
            }
        }
    }
}

// ---------------- edge dtype probe ----------------
__global__ void k_detect(const void* ei_raw, int E, int n) {
    if (threadIdx.x == 0 && blockIdx.x == 0) {
        const long long* p = (const long long*)ei_raw;
        int bad = 0;
        int samples = E < 512 ? E : 512;
        for (int i = 0; i < samples; i++) {
            long long v = p[i];
            if (v < 0 || v >= n) { bad = 1; break; }
        }
        g_i64mode = bad ? 0 : 1;
    }
}
__device__ __forceinline__ int edge_at(const void* ei_raw, size_t idx) {
    if (g_i64mode) return (int)((const long long*)ei_raw)[idx];
    return ((const int*)ei_raw)[idx];
}

// ---------------- graph / elementwise kernels ----------------
__global__ void k_init_deg(int n) {
    int i = blockIdx.x * blockDim.x + threadIdx.x;
    if (i < n) g_deg[i] = 1.0f;
}
__global__ void k_deg(const void* __restrict__ ei, int E, int n) {
    int i = blockIdx.x * blockDim.x + threadIdx.x;
    if (i < E) {
        int t = edge_at(ei, (size_t)E + i);
        t = max(0, min(n - 1, t));
        atomicAdd(&g_deg[t], 1.0f);
    }
}
__global__ void k_dinv(int n) {
    int i = blockIdx.x * blockDim.x + threadIdx.x;
    if (i < n) g_deg[i] = rsqrtf(g_deg[i]);
}
__global__ void k_self(int total) {
    int i = blockIdx.x * blockDim.x + threadIdx.x;
    if (i < total) {
        float d = g_deg[i >> 7];
        g_agg[i] = g_xw[i] * (d * d);
    }
}
__global__ void k_scatter(const void* __restrict__ ei, int E, int n) {
    int gw = (blockIdx.x * blockDim.x + threadIdx.x) >> 5;
    int lane = threadIdx.x & 31;
    if (gw >= E) return;
    int r = edge_at(ei, gw);
    int c = edge_at(ei, (size_t)E + gw);
    r = max(0, min(n - 1, r));
    c = max(0, min(n - 1, c));
    float w = g_deg[r] * g_deg[c];
    const float* src = g_xw  + (size_t)r * G_CH;
    float*       dst = g_agg + (size_t)c * G_CH;
#pragma unroll
    for (int i = 0; i < G_CH / 32; i++)
        atomicAdd(&dst[lane + 32 * i], src[lane + 32 * i] * w);
}
// x1 = relu(agg + b) -> split planes g_x1h/g_x1l
__global__ void k_bias_relu_split(const float* __restrict__ b, int total) {
    int i = blockIdx.x * blockDim.x + threadIdx.x;
    if (i < total) {
        float v = fmaxf(g_agg[i] + b[i & (G_CH - 1)], 0.0f);
        __nv_bfloat16 h, l; split2(v, h, l);
        g_x1h[i] = h;
        g_x1l[i] = l;
    }
}

// ---------------- launch ----------------
extern "C" void kernel_launch(void* const* d_in, const int* in_sizes, int n_in,
                              void* d_out, int out_size) {
    const float* x     = nullptr;  int x_cnt = 0;
    const void*  ei    = nullptr;  int ei_cnt = 0;
    const float* W_gcn = nullptr;
    const float* b_gcn = nullptr;
    const float* W_hid = nullptr;
    const float* b_hid = nullptr;
    const float* W_cls = nullptr;
    const float* b_cls = nullptr;

    int max_cnt = 0;
    for (int i = 0; i < n_in; i++) if (in_sizes[i] > max_cnt) max_cnt = in_sizes[i];
    for (int i = 0; i < n_in; i++) {
        int c = in_sizes[i];
        if      (c == IN_CH * G_CH)  W_gcn = (const float*)d_in[i];
        else if (c == KCAT * HID)    W_hid = (const float*)d_in[i];
        else if (c == HID * NCLS)    W_cls = (const float*)d_in[i];
        else if (c == G_CH)          b_gcn = (const float*)d_in[i];
        else if (c == HID)           b_hid = (const float*)d_in[i];
        else if (c == NCLS)          b_cls = (const float*)d_in[i];
        else if (c == max_cnt && c % IN_CH == 0) { x = (const float*)d_in[i]; x_cnt = c; }
    }
    const int N = x_cnt / IN_CH;

    for (int i = 0; i < n_in; i++) {
        const void* p = d_in[i];
        if (p == (const void*)x || p == (const void*)W_gcn || p == (const void*)W_hid ||
            p == (const void*)W_cls || p == (const void*)b_gcn || p == (const void*)b_hid ||
            p == (const void*)b_cls) continue;
        int c = in_sizes[i];
        if (c != 2 * N) { ei = p; ei_cnt = c; }
        else if (ei == nullptr) { ei = p; ei_cnt = c; }
    }
    const int E = ei_cnt / 2;

    float* h      = (float*)d_out;                 // [N, 512]
    float* logits = h + (size_t)N * HID;           // [N, 79]

    const int mblocks = (N + 127) / 128;

    // 0) probes + pre-splits
    k_detect<<<1, 32>>>(ei, E, N);
    size_t total4 = (size_t)N * IN_CH / 4;
    k_split_x<<<(unsigned)((total4 + 255) / 256), 256>>>((const float4*)x, total4);
    k_split_w<0><<<(G_CH * IN_CH + 255) / 256, 256>>>(W_gcn);
    k_split_w<1><<<(HID * KCAT + 255) / 256, 256>>>(W_hid);
    k_split_w<2><<<(128 * HID + 255) / 256, 256>>>(W_cls);

    // 1) xw = x @ W_gcn -> g_xw (fp32)
    tc_gemm<0, 0, false, false, false, 1><<<dim3(mblocks, 1), 256>>>(nullptr, nullptr, N, G_CH);

    // 2) degree + dinv
    k_init_deg<<<(N + 255) / 256, 256>>>(N);
    k_deg<<<(E + 255) / 256, 256>>>(ei, E, N);
    k_dinv<<<(N + 255) / 256, 256>>>(N);

    // 3) aggregation -> x1 split planes
    int tot = N * G_CH;
    k_self<<<(tot + 255) / 256, 256>>>(tot);
    k_scatter<<<(E + 7) / 8, 256>>>(ei, E, N);
    k_bias_relu_split<<<(tot + 255) / 256, 256>>>(b_gcn, tot);

    // 4) h = relu([x | x1] @ W_hid + b_hid) -> d_out (+ split planes for GEMM3)
    tc_gemm<1, 1, true, true, true, 0><<<dim3(mblocks, 4), 256>>>(b_hid, h, N, HID);

    // 5) logits = h @ W_cls + b_cls
    tc_gemm<2, 2, true, false, false, 0><<<dim3(mblocks, 1), 256>>>(b_cls, logits, N, NCLS);
}

// round 9
// speedup vs baseline: 3.7292x; 1.0401x over previous
#include <cuda_runtime.h>
#include <cuda_bf16.h>
#include <cstdint>

#define N_NODES 100000
#define N_PAD   100096
#define IN_CH   1280
#define G_CH    128
#define HID     512
#define NCLS    79
#define KCAT    (IN_CH + G_CH)

// ---------------- scratch (device globals; no allocation allowed) ----------------
__device__ float g_xw [(size_t)N_PAD * G_CH];
__device__ float g_agg[(size_t)N_PAD * G_CH];
__device__ float g_deg[N_NODES];
__device__ int   g_i64mode;

__device__ __nv_bfloat16 g_xh [(size_t)N_PAD * IN_CH];
__device__ __nv_bfloat16 g_xl [(size_t)N_PAD * IN_CH];
__device__ __nv_bfloat16 g_x1h[(size_t)N_PAD * G_CH];
__device__ __nv_bfloat16 g_x1l[(size_t)N_PAD * G_CH];
__device__ __nv_bfloat16 g_hh [(size_t)N_PAD * HID];
__device__ __nv_bfloat16 g_hl [(size_t)N_PAD * HID];
__device__ __nv_bfloat16 g_wgh[G_CH * IN_CH],  g_wgl[G_CH * IN_CH];
__device__ __nv_bfloat16 g_whh[HID * KCAT],    g_whl[HID * KCAT];
__device__ __nv_bfloat16 g_wch[128 * HID],     g_wcl[128 * HID];

// ---------------- PTX helpers ----------------
__device__ __forceinline__ uint32_t smem_u32(const void* p) {
    uint32_t a;
    asm("{ .reg .u64 t; cvta.to.shared.u64 t, %1; cvt.u32.u64 %0, t; }" : "=r"(a) : "l"(p));
    return a;
}
__device__ __forceinline__ void cp16(uint32_t dst, const void* src) {
    asm volatile("cp.async.cg.shared.global [%0], [%1], 16;" :: "r"(dst), "l"(src));
}
__device__ __forceinline__ void ldm_x4(uint32_t* r, uint32_t addr) {
    asm volatile("ldmatrix.sync.aligned.m8n8.x4.shared.b16 {%0,%1,%2,%3}, [%4];"
        : "=r"(r[0]), "=r"(r[1]), "=r"(r[2]), "=r"(r[3]) : "r"(addr));
}
__device__ __forceinline__ void mma16816(float* c, const uint32_t* a, const uint32_t* b) {
    asm volatile("mma.sync.aligned.m16n8k16.row.col.f32.bf16.bf16.f32 "
        "{%0,%1,%2,%3}, {%4,%5,%6,%7}, {%8,%9}, {%0,%1,%2,%3};"
        : "+f"(c[0]), "+f"(c[1]), "+f"(c[2]), "+f"(c[3])
        : "r"(a[0]), "r"(a[1]), "r"(a[2]), "r"(a[3]), "r"(b[0]), "r"(b[1]));
}
__device__ __forceinline__ void split2(float v, __nv_bfloat16& h, __nv_bfloat16& l) {
    h = __float2bfloat16(v);
    l = __float2bfloat16(v - __bfloat162float(h));
}

// ---------------- split preprocessing ----------------
__global__ void k_split_x(const float4* __restrict__ x4, size_t total4) {
    size_t i = (size_t)blockIdx.x * blockDim.x + threadIdx.x;
    if (i >= total4) return;
    float4 v = x4[i];
    __nv_bfloat16 h0, h1, h2, h3, l0, l1, l2, l3;
    split2(v.x, h0, l0); split2(v.y, h1, l1); split2(v.z, h2, l2); split2(v.w, h3, l3);
    __nv_bfloat162* ph = reinterpret_cast<__nv_bfloat162*>(&g_xh[i * 4]);
    ph[0] = __nv_bfloat162(h0, h1); ph[1] = __nv_bfloat162(h2, h3);
    __nv_bfloat162* pl = reinterpret_cast<__nv_bfloat162*>(&g_xl[i * 4]);
    pl[0] = __nv_bfloat162(l0, l1); pl[1] = __nv_bfloat162(l2, l3);
}

template<int WMODE>
__global__ void k_split_w(const float* __restrict__ W) {
    constexpr int KD   = (WMODE == 0) ? IN_CH : (WMODE == 1) ? KCAT : HID;
    constexpr int ND   = (WMODE == 0) ? G_CH  : (WMODE == 1) ? HID  : NCLS;
    constexpr int NPAD = (WMODE == 0) ? G_CH  : (WMODE == 1) ? HID  : 128;
    int idx = blockIdx.x * blockDim.x + threadIdx.x;
    if (idx >= NPAD * KD) return;
    int n = idx / KD, k = idx % KD;
    float v = (n < ND) ? __ldg(&W[(size_t)k * ND + n]) : 0.0f;
    __nv_bfloat16 h, l; split2(v, h, l);
    if (WMODE == 0) { g_wgh[idx] = h; g_wgl[idx] = l; }
    if (WMODE == 1) { g_whh[idx] = h; g_whl[idx] = l; }
    if (WMODE == 2) { g_wch[idx] = h; g_wcl[idx] = l; }
}

// ---------------- pipelined split-bf16 tensor-core GEMM ----------------
#define RS 40                    // smem row stride in bf16 (32 data + 8 pad)
#define PLANE_B  10240           // 128*RS*2 bytes per plane
#define STAGE_B  40960           // 4 planes
#define SMEM_DYN 81920           // 2 stages

template<int AM, int BMODE, bool BIAS, bool RELU, bool HSPLIT, int CM>
__global__ void __launch_bounds__(256, 2)
tc_gemm(const float* __restrict__ bias, float* __restrict__ Cp, int M, int Nout)
{
    extern __shared__ __align__(16) char dsm[];
    const uint32_t base = smem_u32(dsm);

    const int tid  = threadIdx.x;
    const int wid  = tid >> 5;
    const int lane = tid & 31;
    const int wm = wid >> 2;
    const int wn = wid & 3;
    const int m0 = blockIdx.x * 128;
    const int n0 = blockIdx.y * 128;

    float acc[4][4][4];
#pragma unroll
    for (int i = 0; i < 4; i++)
#pragma unroll
        for (int j = 0; j < 4; j++)
#pragma unroll
            for (int r = 0; r < 4; r++) acc[i][j][r] = 0.0f;

    constexpr int K  = (AM == 0) ? IN_CH : (AM == 1) ? KCAT : HID;
    constexpr int Kb = (BMODE == 0) ? IN_CH : (BMODE == 1) ? KCAT : HID;
    constexpr int nchunks = K >> 5;

    const int lrow = lane & 15;
    const int lko  = (lane >> 4) << 3;

    // issue cp.async for chunk ch into stage stg, then commit
    auto issue = [&](int ch, int stg) {
        const int k0 = ch << 5;
        const __nv_bfloat16 *pAh, *pAl; int Kd, koff;
        if (AM == 0) { pAh = g_xh; pAl = g_xl; Kd = IN_CH; koff = k0; }
        else if (AM == 2) { pAh = g_hh; pAl = g_hl; Kd = HID; koff = k0; }
        else {
            if (k0 < IN_CH) { pAh = g_xh;  pAl = g_xl;  Kd = IN_CH; koff = k0; }
            else            { pAh = g_x1h; pAl = g_x1l; Kd = G_CH;  koff = k0 - IN_CH; }
        }
        const __nv_bfloat16 *pBh, *pBl;
        if (BMODE == 0) { pBh = g_wgh; pBl = g_wgl; }
        else if (BMODE == 1) { pBh = g_whh; pBl = g_whl; }
        else { pBh = g_wch; pBl = g_wcl; }

        const uint32_t sb = base + stg * STAGE_B;
#pragma unroll
        for (int it = 0; it < 2; it++) {
            int o = tid + it * 256;
            int row = o >> 2, grp = o & 3;
            uint32_t so = (uint32_t)(row * (RS * 2) + grp * 16);
            size_t aoff = (size_t)(m0 + row) * Kd + koff + grp * 8;
            cp16(sb + so,               pAh + aoff);
            cp16(sb + PLANE_B + so,     pAl + aoff);
            size_t boff = (size_t)(n0 + row) * Kb + k0 + grp * 8;
            cp16(sb + 2 * PLANE_B + so, pBh + boff);
            cp16(sb + 3 * PLANE_B + so, pBl + boff);
        }
        asm volatile("cp.async.commit_group;");
    };

    issue(0, 0);
    for (int ch = 0; ch < nchunks; ch++) {
        const int stg = ch & 1;
        if (ch + 1 < nchunks) {
            issue(ch + 1, stg ^ 1);
            asm volatile("cp.async.wait_group 1;");
        } else {
            asm volatile("cp.async.wait_group 0;");
        }
        __syncthreads();

        const uint32_t uAh = base + stg * STAGE_B;
        const uint32_t uAl = uAh + PLANE_B;
        const uint32_t uBh = uAh + 2 * PLANE_B;
        const uint32_t uBl = uAh + 3 * PLANE_B;

#pragma unroll
        for (int s = 0; s < 2; s++) {
            const int ks = s * 16 + lko;
            uint32_t bh[4][2], bl[4][2];
#pragma unroll
            for (int g = 0; g < 2; g++) {
                uint32_t r[4];
                uint32_t addr = uBh + ((wn * 32 + g * 16 + lrow) * RS + ks) * 2;
                ldm_x4(r, addr);
                bh[2 * g][0] = r[0]; bh[2 * g][1] = r[2];
                bh[2 * g + 1][0] = r[1]; bh[2 * g + 1][1] = r[3];
                addr = uBl + ((wn * 32 + g * 16 + lrow) * RS + ks) * 2;
                ldm_x4(r, addr);
                bl[2 * g][0] = r[0]; bl[2 * g][1] = r[2];
                bl[2 * g + 1][0] = r[1]; bl[2 * g + 1][1] = r[3];
            }
            uint32_t ah[4][4], al[4][4];
#pragma unroll
            for (int mt = 0; mt < 4; mt++) {
                uint32_t addr = uAh + ((wm * 64 + mt * 16 + lrow) * RS + ks) * 2;
                ldm_x4(ah[mt], addr);
                addr = uAl + ((wm * 64 + mt * 16 + lrow) * RS + ks) * 2;
                ldm_x4(al[mt], addr);
            }
#pragma unroll
            for (int mt = 0; mt < 4; mt++)
#pragma unroll
                for (int nt = 0; nt < 4; nt++) {
                    mma16816(acc[mt][nt], ah[mt], bh[nt]);
                    mma16816(acc[mt][nt], ah[mt], bl[nt]);
                    mma16816(acc[mt][nt], al[mt], bh[nt]);
                }
        }
        __syncthreads();
    }

    // ---- epilogue ----
    const int qr = lane >> 2;
    const int qc = (lane & 3) * 2;
#pragma unroll
    for (int mt = 0; mt < 4; mt++) {
#pragma unroll
        for (int nt = 0; nt < 4; nt++) {
#pragma unroll
            for (int half = 0; half < 2; half++) {
                int gm = m0 + wm * 64 + mt * 16 + qr + half * 8;
                if (gm >= M) continue;
#pragma unroll
                for (int j = 0; j < 2; j++) {
                    int gn = n0 + wn * 32 + nt * 8 + qc + j;
                    if (gn >= Nout) continue;
                    float v = acc[mt][nt][half * 2 + j];
                    if (BIAS) v += __ldg(&bias[gn]);
                    if (RELU) v = fmaxf(v, 0.0f);
                    if (CM == 1) g_xw[(size_t)gm * Nout + gn] = v;
                    else         Cp[(size_t)gm * Nout + gn] = v;
                    if (HSPLIT) {
                        __nv_bfloat16 hb, lb; split2(v, hb, lb);
                        g_hh[(size_t)gm * HID + gn] = hb;
                        g_hl[(size_t)gm * HID + gn] = lb;
                    }
                }
            }
        }
    }
}

// ---------------- edge dtype probe ----------------
__global__ void k_detect(const void* ei_raw, int E, int n) {
    if (threadIdx.x == 0 && blockIdx.x == 0) {
        const long long* p = (const long long*)ei_raw;
        int bad = 0;
        int samples = E < 512 ? E : 512;
        for (int i = 0; i < samples; i++) {
            long long v = p[i];
            if (v < 0 || v >= n) { bad = 1; break; }
        }
        g_i64mode = bad ? 0 : 1;
    }
}
__device__ __forceinline__ int edge_at(const void* ei_raw, size_t idx) {
    if (g_i64mode) return (int)((const long long*)ei_raw)[idx];
    return ((const int*)ei_raw)[idx];
}

// ---------------- graph / elementwise kernels ----------------
__global__ void k_init_deg(int n) {
    int i = blockIdx.x * blockDim.x + threadIdx.x;
    if (i < n) g_deg[i] = 1.0f;
}
__global__ void k_deg(const void* __restrict__ ei, int E, int n) {
    int i = blockIdx.x * blockDim.x + threadIdx.x;
    if (i < E) {
        int t = edge_at(ei, (size_t)E + i);
        t = max(0, min(n - 1, t));
        atomicAdd(&g_deg[t], 1.0f);
    }
}
__global__ void k_dinv(int n) {
    int i = blockIdx.x * blockDim.x + threadIdx.x;
    if (i < n) g_deg[i] = rsqrtf(g_deg[i]);
}
__global__ void k_self(int total) {
    int i = blockIdx.x * blockDim.x + threadIdx.x;
    if (i < total) {
        float d = g_deg[i >> 7];
        g_agg[i] = g_xw[i] * (d * d);
    }
}
__global__ void k_scatter(const void* __restrict__ ei, int E, int n) {
    int gw = (blockIdx.x * blockDim.x + threadIdx.x) >> 5;
    int lane = threadIdx.x & 31;
    if (gw >= E) return;
    int r = edge_at(ei, gw);
    int c = edge_at(ei, (size_t)E + gw);
    r = max(0, min(n - 1, r));
    c = max(0, min(n - 1, c));
    float w = g_deg[r] * g_deg[c];
    const float* src = g_xw  + (size_t)r * G_CH;
    float*       dst = g_agg + (size_t)c * G_CH;
#pragma unroll
    for (int i = 0; i < G_CH / 32; i++)
        atomicAdd(&dst[lane + 32 * i], src[lane + 32 * i] * w);
}
__global__ void k_bias_relu_split(const float* __restrict__ b, int total) {
    int i = blockIdx.x * blockDim.x + threadIdx.x;
    if (i < total) {
        float v = fmaxf(g_agg[i] + b[i & (G_CH - 1)], 0.0f);
        __nv_bfloat16 h, l; split2(v, h, l);
        g_x1h[i] = h;
        g_x1l[i] = l;
    }
}

// ---------------- launch ----------------
extern "C" void kernel_launch(void* const* d_in, const int* in_sizes, int n_in,
                              void* d_out, int out_size) {
    const float* x     = nullptr;  int x_cnt = 0;
    const void*  ei    = nullptr;  int ei_cnt = 0;
    const float* W_gcn = nullptr;
    const float* b_gcn = nullptr;
    const float* W_hid = nullptr;
    const float* b_hid = nullptr;
    const float* W_cls = nullptr;
    const float* b_cls = nullptr;

    int max_cnt = 0;
    for (int i = 0; i < n_in; i++) if (in_sizes[i] > max_cnt) max_cnt = in_sizes[i];
    for (int i = 0; i < n_in; i++) {
        int c = in_sizes[i];
        if      (c == IN_CH * G_CH)  W_gcn = (const float*)d_in[i];
        else if (c == KCAT * HID)    W_hid = (const float*)d_in[i];
        else if (c == HID * NCLS)    W_cls = (const float*)d_in[i];
        else if (c == G_CH)          b_gcn = (const float*)d_in[i];
        else if (c == HID)           b_hid = (const float*)d_in[i];
        else if (c == NCLS)          b_cls = (const float*)d_in[i];
        else if (c == max_cnt && c % IN_CH == 0) { x = (const float*)d_in[i]; x_cnt = c; }
    }
    const int N = x_cnt / IN_CH;

    for (int i = 0; i < n_in; i++) {
        const void* p = d_in[i];
        if (p == (const void*)x || p == (const void*)W_gcn || p == (const void*)W_hid ||
            p == (const void*)W_cls || p == (const void*)b_gcn || p == (const void*)b_hid ||
            p == (const void*)b_cls) continue;
        int c = in_sizes[i];
        if (c != 2 * N) { ei = p; ei_cnt = c; }
        else if (ei == nullptr) { ei = p; ei_cnt = c; }
    }
    const int E = ei_cnt / 2;

    float* h      = (float*)d_out;
    float* logits = h + (size_t)N * HID;

    const int mblocks = (N + 127) / 128;

    // allow 80KB dynamic smem (immediate host-side attribute set; capture-safe)
    cudaFuncSetAttribute(tc_gemm<0, 0, false, false, false, 1>,
                         cudaFuncAttributeMaxDynamicSharedMemorySize, SMEM_DYN);
    cudaFuncSetAttribute(tc_gemm<1, 1, true, true, true, 0>,
                         cudaFuncAttributeMaxDynamicSharedMemorySize, SMEM_DYN);
    cudaFuncSetAttribute(tc_gemm<2, 2, true, false, false, 0>,
                         cudaFuncAttributeMaxDynamicSharedMemorySize, SMEM_DYN);

    // 0) probes + pre-splits
    k_detect<<<1, 32>>>(ei, E, N);
    size_t total4 = (size_t)N * IN_CH / 4;
    k_split_x<<<(unsigned)((total4 + 255) / 256), 256>>>((const float4*)x, total4);
    k_split_w<0><<<(G_CH * IN_CH + 255) / 256, 256>>>(W_gcn);
    k_split_w<1><<<(HID * KCAT + 255) / 256, 256>>>(W_hid);
    k_split_w<2><<<(128 * HID + 255) / 256, 256>>>(W_cls);

    // 1) xw = x @ W_gcn -> g_xw (fp32)
    tc_gemm<0, 0, false, false, false, 1><<<dim3(mblocks, 1), 256, SMEM_DYN>>>(nullptr, nullptr, N, G_CH);

    // 2) degree + dinv
    k_init_deg<<<(N + 255) / 256, 256>>>(N);
    k_deg<<<(E + 255) / 256, 256>>>(ei, E, N);
    k_dinv<<<(N + 255) / 256, 256>>>(N);

    // 3) aggregation -> x1 split planes
    int tot = N * G_CH;
    k_self<<<(tot + 255) / 256, 256>>>(tot);
    k_scatter<<<(E + 7) / 8, 256>>>(ei, E, N);
    k_bias_relu_split<<<(tot + 255) / 256, 256>>>(b_gcn, tot);

    // 4) h = relu([x | x1] @ W_hid + b_hid) -> d_out (+ split planes)
    tc_gemm<1, 1, true, true, true, 0><<<dim3(mblocks, 4), 256, SMEM_DYN>>>(b_hid, h, N, HID);

    // 5) logits = h @ W_cls + b_cls
    tc_gemm<2, 2, true, false, false, 0><<<dim3(mblocks, 1), 256, SMEM_DYN>>>(b_cls, logits, N, NCLS);
}

// round 10
// speedup vs baseline: 7.3718x; 1.9768x over previous
#include <cuda_runtime.h>
#include <cuda_fp16.h>
#include <cstdint>

#define N_NODES 100000
#define N_PAD   100096
#define IN_CH   1280
#define G_CH    128
#define HID     512
#define NCLS    79
#define KCAT    (IN_CH + G_CH)

// ---------------- scratch (device globals; no allocation allowed) ----------------
__device__ float g_xw [(size_t)N_PAD * G_CH];
__device__ float g_agg[(size_t)N_PAD * G_CH];
__device__ float g_deg[N_NODES];
__device__ int   g_i64mode;

// fp16 operand planes
__device__ __half g_xf [(size_t)N_PAD * IN_CH];
__device__ __half g_x1f[(size_t)N_PAD * G_CH];
__device__ __half g_hf [(size_t)N_PAD * HID];
__device__ __half g_wgf[G_CH * IN_CH];
__device__ __half g_whf[HID * KCAT];
__device__ __half g_wcf[128 * HID];          // W_cls transposed, n padded to 128

// ---------------- PTX helpers ----------------
__device__ __forceinline__ uint32_t smem_u32(const void* p) {
    uint32_t a;
    asm("{ .reg .u64 t; cvta.to.shared.u64 t, %1; cvt.u32.u64 %0, t; }" : "=r"(a) : "l"(p));
    return a;
}
__device__ __forceinline__ void cp16(uint32_t dst, const void* src) {
    asm volatile("cp.async.cg.shared.global [%0], [%1], 16;" :: "r"(dst), "l"(src));
}
__device__ __forceinline__ void ldm_x4(uint32_t* r, uint32_t addr) {
    asm volatile("ldmatrix.sync.aligned.m8n8.x4.shared.b16 {%0,%1,%2,%3}, [%4];"
        : "=r"(r[0]), "=r"(r[1]), "=r"(r[2]), "=r"(r[3]) : "r"(addr));
}
__device__ __forceinline__ void mma16816(float* c, const uint32_t* a, const uint32_t* b) {
    asm volatile("mma.sync.aligned.m16n8k16.row.col.f32.f16.f16.f32 "
        "{%0,%1,%2,%3}, {%4,%5,%6,%7}, {%8,%9}, {%0,%1,%2,%3};"
        : "+f"(c[0]), "+f"(c[1]), "+f"(c[2]), "+f"(c[3])
        : "r"(a[0]), "r"(a[1]), "r"(a[2]), "r"(a[3]), "r"(b[0]), "r"(b[1]));
}

// ---------------- conversion preprocessing ----------------
__global__ void k_conv_x(const float4* __restrict__ x4, size_t total4) {
    size_t i = (size_t)blockIdx.x * blockDim.x + threadIdx.x;
    if (i >= total4) return;
    float4 v = x4[i];
    __half2* p = reinterpret_cast<__half2*>(&g_xf[i * 4]);
    p[0] = __floats2half2_rn(v.x, v.y);
    p[1] = __floats2half2_rn(v.z, v.w);
}

// WMODE 0: W_gcn [1280][128] -> g_wgf [128][1280]
// WMODE 1: W_hid [1408][512] -> g_whf [512][1408]
// WMODE 2: W_cls [512][79]   -> g_wcf [128][512] (rows 79..127 zero)
template<int WMODE>
__global__ void k_conv_w(const float* __restrict__ W) {
    constexpr int KD   = (WMODE == 0) ? IN_CH : (WMODE == 1) ? KCAT : HID;
    constexpr int ND   = (WMODE == 0) ? G_CH  : (WMODE == 1) ? HID  : NCLS;
    constexpr int NPAD = (WMODE == 0) ? G_CH  : (WMODE == 1) ? HID  : 128;
    int idx = blockIdx.x * blockDim.x + threadIdx.x;
    if (idx >= NPAD * KD) return;
    int n = idx / KD, k = idx % KD;
    float v = (n < ND) ? __ldg(&W[(size_t)k * ND + n]) : 0.0f;
    if (WMODE == 0) g_wgf[idx] = __float2half_rn(v);
    if (WMODE == 1) g_whf[idx] = __float2half_rn(v);
    if (WMODE == 2) g_wcf[idx] = __float2half_rn(v);
}

// ---------------- pipelined fp16 tensor-core GEMM ----------------
#define RS 40                    // smem row stride in halves (32 data + 8 pad)
#define PLANE_B  10240           // 128*RS*2 bytes
#define STAGE_B  20480           // A + B planes
#define SMEM_DYN 40960           // 2 stages (< 48KB default limit)

// AM: 0 = x (K=1280), 1 = [x | x1] (K=1408), 2 = h (K=512)
// BMODE: 0 = W_gcn, 1 = W_hid, 2 = W_cls.  CM: 0 -> Cp, 1 -> g_xw.  HOUT: also write g_hf.
template<int AM, int BMODE, bool BIAS, bool RELU, bool HOUT, int CM>
__global__ void __launch_bounds__(256, 2)
tc_gemm(const float* __restrict__ bias, float* __restrict__ Cp, int M, int Nout)
{
    extern __shared__ __align__(16) char dsm[];
    const uint32_t base = smem_u32(dsm);

    const int tid  = threadIdx.x;
    const int wid  = tid >> 5;
    const int lane = tid & 31;
    const int wm = wid >> 2;
    const int wn = wid & 3;
    const int m0 = blockIdx.x * 128;
    const int n0 = blockIdx.y * 128;

    float acc[4][4][4];
#pragma unroll
    for (int i = 0; i < 4; i++)
#pragma unroll
        for (int j = 0; j < 4; j++)
#pragma unroll
            for (int r = 0; r < 4; r++) acc[i][j][r] = 0.0f;

    constexpr int K  = (AM == 0) ? IN_CH : (AM == 1) ? KCAT : HID;
    constexpr int Kb = (BMODE == 0) ? IN_CH : (BMODE == 1) ? KCAT : HID;
    constexpr int nchunks = K >> 5;

    const int lrow = lane & 15;
    const int lko  = (lane >> 4) << 3;

    auto issue = [&](int ch, int stg) {
        const int k0 = ch << 5;
        const __half* pA; int Kd, koff;
        if (AM == 0) { pA = g_xf; Kd = IN_CH; koff = k0; }
        else if (AM == 2) { pA = g_hf; Kd = HID; koff = k0; }
        else {
            if (k0 < IN_CH) { pA = g_xf;  Kd = IN_CH; koff = k0; }
            else            { pA = g_x1f; Kd = G_CH;  koff = k0 - IN_CH; }
        }
        const __half* pB = (BMODE == 0) ? g_wgf : (BMODE == 1) ? g_whf : g_wcf;

        const uint32_t sb = base + stg * STAGE_B;
#pragma unroll
        for (int it = 0; it < 2; it++) {
            int o = tid + it * 256;
            int row = o >> 2, grp = o & 3;
            uint32_t so = (uint32_t)(row * (RS * 2) + grp * 16);
            cp16(sb + so,           pA + (size_t)(m0 + row) * Kd + koff + grp * 8);
            cp16(sb + PLANE_B + so, pB + (size_t)(n0 + row) * Kb + k0 + grp * 8);
        }
        asm volatile("cp.async.commit_group;");
    };

    issue(0, 0);
    for (int ch = 0; ch < nchunks; ch++) {
        const int stg = ch & 1;
        if (ch + 1 < nchunks) {
            issue(ch + 1, stg ^ 1);
            asm volatile("cp.async.wait_group 1;");
        } else {
            asm volatile("cp.async.wait_group 0;");
        }
        __syncthreads();

        const uint32_t uA = base + stg * STAGE_B;
        const uint32_t uB = uA + PLANE_B;

#pragma unroll
        for (int s = 0; s < 2; s++) {
            const int ks = s * 16 + lko;
            uint32_t bt[4][2];
#pragma unroll
            for (int g = 0; g < 2; g++) {
                uint32_t r[4];
                uint32_t addr = uB + ((wn * 32 + g * 16 + lrow) * RS + ks) * 2;
                ldm_x4(r, addr);
                bt[2 * g][0] = r[0]; bt[2 * g][1] = r[2];
                bt[2 * g + 1][0] = r[1]; bt[2 * g + 1][1] = r[3];
            }
            uint32_t at[4][4];
#pragma unroll
            for (int mt = 0; mt < 4; mt++) {
                uint32_t addr = uA + ((wm * 64 + mt * 16 + lrow) * RS + ks) * 2;
                ldm_x4(at[mt], addr);
            }
#pragma unroll
            for (int mt = 0; mt < 4; mt++)
#pragma unroll
                for (int nt = 0; nt < 4; nt++)
                    mma16816(acc[mt][nt], at[mt], bt[nt]);
        }
        __syncthreads();
    }

    // ---- epilogue ----
    const int qr = lane >> 2;
    const int qc = (lane & 3) * 2;
#pragma unroll
    for (int mt = 0; mt < 4; mt++) {
#pragma unroll
        for (int nt = 0; nt < 4; nt++) {
#pragma unroll
            for (int half = 0; half < 2; half++) {
                int gm = m0 + wm * 64 + mt * 16 + qr + half * 8;
                if (gm >= M) continue;
#pragma unroll
                for (int j = 0; j < 2; j++) {
                    int gn = n0 + wn * 32 + nt * 8 + qc + j;
                    if (gn >= Nout) continue;
                    float v = acc[mt][nt][half * 2 + j];
                    if (BIAS) v += __ldg(&bias[gn]);
                    if (RELU) v = fmaxf(v, 0.0f);
                    if (CM == 1) g_xw[(size_t)gm * Nout + gn] = v;
                    else         Cp[(size_t)gm * Nout + gn] = v;
                    if (HOUT) g_hf[(size_t)gm * HID + gn] = __float2half_rn(v);
                }
            }
        }
    }
}

// ---------------- edge dtype probe ----------------
__global__ void k_detect(const void* ei_raw, int E, int n) {
    if (threadIdx.x == 0 && blockIdx.x == 0) {
        const long long* p = (const long long*)ei_raw;
        int bad = 0;
        int samples = E < 512 ? E : 512;
        for (int i = 0; i < samples; i++) {
            long long v = p[i];
            if (v < 0 || v >= n) { bad = 1; break; }
        }
        g_i64mode = bad ? 0 : 1;
    }
}
__device__ __forceinline__ int edge_at(const void* ei_raw, size_t idx) {
    if (g_i64mode) return (int)((const long long*)ei_raw)[idx];
    return ((const int*)ei_raw)[idx];
}

// ---------------- graph / elementwise kernels ----------------
__global__ void k_init_deg(int n) {
    int i = blockIdx.x * blockDim.x + threadIdx.x;
    if (i < n) g_deg[i] = 1.0f;
}
__global__ void k_deg(const void* __restrict__ ei, int E, int n) {
    int i = blockIdx.x * blockDim.x + threadIdx.x;
    if (i < E) {
        int t = edge_at(ei, (size_t)E + i);
        t = max(0, min(n - 1, t));
        atomicAdd(&g_deg[t], 1.0f);
    }
}
__global__ void k_dinv(int n) {
    int i = blockIdx.x * blockDim.x + threadIdx.x;
    if (i < n) g_deg[i] = rsqrtf(g_deg[i]);
}
__global__ void k_self(int total) {
    int i = blockIdx.x * blockDim.x + threadIdx.x;
    if (i < total) {
        float d = g_deg[i >> 7];
        g_agg[i] = g_xw[i] * (d * d);
    }
}
__global__ void k_scatter(const void* __restrict__ ei, int E, int n) {
    int gw = (blockIdx.x * blockDim.x + threadIdx.x) >> 5;
    int lane = threadIdx.x & 31;
    if (gw >= E) return;
    int r = edge_at(ei, gw);
    int c = edge_at(ei, (size_t)E + gw);
    r = max(0, min(n - 1, r));
    c = max(0, min(n - 1, c));
    float w = g_deg[r] * g_deg[c];
    const float* src = g_xw  + (size_t)r * G_CH;
    float*       dst = g_agg + (size_t)c * G_CH;
#pragma unroll
    for (int i = 0; i < G_CH / 32; i++)
        atomicAdd(&dst[lane + 32 * i], src[lane + 32 * i] * w);
}
// x1 = relu(agg + b) -> fp16 plane
__global__ void k_bias_relu_conv(const float* __restrict__ b, int total) {
    int i = blockIdx.x * blockDim.x + threadIdx.x;
    if (i < total) {
        float v = fmaxf(g_agg[i] + b[i & (G_CH - 1)], 0.0f);
        g_x1f[i] = __float2half_rn(v);
    }
}

// ---------------- launch ----------------
extern "C" void kernel_launch(void* const* d_in, const int* in_sizes, int n_in,
                              void* d_out, int out_size) {
    const float* x     = nullptr;  int x_cnt = 0;
    const void*  ei    = nullptr;  int ei_cnt = 0;
    const float* W_gcn = nullptr;
    const float* b_gcn = nullptr;
    const float* W_hid = nullptr;
    const float* b_hid = nullptr;
    const float* W_cls = nullptr;
    const float* b_cls = nullptr;

    int max_cnt = 0;
    for (int i = 0; i < n_in; i++) if (in_sizes[i] > max_cnt) max_cnt = in_sizes[i];
    for (int i = 0; i < n_in; i++) {
        int c = in_sizes[i];
        if      (c == IN_CH * G_CH)  W_gcn = (const float*)d_in[i];
        else if (c == KCAT * HID)    W_hid = (const float*)d_in[i];
        else if (c == HID * NCLS)    W_cls = (const float*)d_in[i];
        else if (c == G_CH)          b_gcn = (const float*)d_in[i];
        else if (c == HID)           b_hid = (const float*)d_in[i];
        else if (c == NCLS)          b_cls = (const float*)d_in[i];
        else if (c == max_cnt && c % IN_CH == 0) { x = (const float*)d_in[i]; x_cnt = c; }
    }
    const int N = x_cnt / IN_CH;

    for (int i = 0; i < n_in; i++) {
        const void* p = d_in[i];
        if (p == (const void*)x || p == (const void*)W_gcn || p == (const void*)W_hid ||
            p == (const void*)W_cls || p == (const void*)b_gcn || p == (const void*)b_hid ||
            p == (const void*)b_cls) continue;
        int c = in_sizes[i];
        if (c != 2 * N) { ei = p; ei_cnt = c; }
        else if (ei == nullptr) { ei = p; ei_cnt = c; }
    }
    const int E = ei_cnt / 2;

    float* h      = (float*)d_out;
    float* logits = h + (size_t)N * HID;

    const int mblocks = (N + 127) / 128;

    // 0) probes + fp16 conversions
    k_detect<<<1, 32>>>(ei, E, N);
    size_t total4 = (size_t)N * IN_CH / 4;
    k_conv_x<<<(unsigned)((total4 + 255) / 256), 256>>>((const float4*)x, total4);
    k_conv_w<0><<<(G_CH * IN_CH + 255) / 256, 256>>>(W_gcn);
    k_conv_w<1><<<(HID * KCAT + 255) / 256, 256>>>(W_hid);
    k_conv_w<2><<<(128 * HID + 255) / 256, 256>>>(W_cls);

    // 1) xw = x @ W_gcn -> g_xw (fp32)
    tc_gemm<0, 0, false, false, false, 1><<<dim3(mblocks, 1), 256, SMEM_DYN>>>(nullptr, nullptr, N, G_CH);

    // 2) degree + dinv
    k_init_deg<<<(N + 255) / 256, 256>>>(N);
    k_deg<<<(E + 255) / 256, 256>>>(ei, E, N);
    k_dinv<<<(N + 255) / 256, 256>>>(N);

    // 3) aggregation -> x1 fp16 plane
    int tot = N * G_CH;
    k_self<<<(tot + 255) / 256, 256>>>(tot);
    k_scatter<<<(E + 7) / 8, 256>>>(ei, E, N);
    k_bias_relu_conv<<<(tot + 255) / 256, 256>>>(b_gcn, tot);

    // 4) h = relu([x | x1] @ W_hid + b_hid) -> d_out (+ fp16 plane for GEMM3)
    tc_gemm<1, 1, true, true, true, 0><<<dim3(mblocks, 4), 256, SMEM_DYN>>>(b_hid, h, N, HID);

    // 5) logits = h @ W_cls + b_cls
    tc_gemm<2, 2, true, false, false, 0><<<dim3(mblocks, 1), 256, SMEM_DYN>>>(b_cls, logits, N, NCLS);
}

// round 11
// speedup vs baseline: 8.1590x; 1.1068x over previous
#include <cuda_runtime.h>
#include <cuda_fp16.h>
#include <cstdint>

#define N_NODES 100000
#define N_PAD   100096
#define IN_CH   1280
#define G_CH    128
#define HID     512
#define NCLS    79
#define KCAT    (IN_CH + G_CH)

// ---------------- scratch (device globals; no allocation allowed) ----------------
__device__ float  g_deg[N_NODES];
__device__ int    g_i64mode;
__device__ __half g_xwf [(size_t)N_PAD * G_CH];   // x @ W_gcn (fp16)
__device__ __half g_aggh[(size_t)N_PAD * G_CH];   // fp16 accumulation target
__device__ __half g_xf [(size_t)N_PAD * IN_CH];
__device__ __half g_x1f[(size_t)N_PAD * G_CH];
__device__ __half g_hf [(size_t)N_PAD * HID];
__device__ __half g_wgf[G_CH * IN_CH];
__device__ __half g_whf[HID * KCAT];
__device__ __half g_wcf[128 * HID];

// ---------------- PTX helpers ----------------
__device__ __forceinline__ uint32_t smem_u32(const void* p) {
    uint32_t a;
    asm("{ .reg .u64 t; cvta.to.shared.u64 t, %1; cvt.u32.u64 %0, t; }" : "=r"(a) : "l"(p));
    return a;
}
__device__ __forceinline__ void cp16(uint32_t dst, const void* src) {
    asm volatile("cp.async.cg.shared.global [%0], [%1], 16;" :: "r"(dst), "l"(src));
}
__device__ __forceinline__ void ldm_x4(uint32_t* r, uint32_t addr) {
    asm volatile("ldmatrix.sync.aligned.m8n8.x4.shared.b16 {%0,%1,%2,%3}, [%4];"
        : "=r"(r[0]), "=r"(r[1]), "=r"(r[2]), "=r"(r[3]) : "r"(addr));
}
__device__ __forceinline__ void mma16816(float* c, const uint32_t* a, const uint32_t* b) {
    asm volatile("mma.sync.aligned.m16n8k16.row.col.f32.f16.f16.f32 "
        "{%0,%1,%2,%3}, {%4,%5,%6,%7}, {%8,%9}, {%0,%1,%2,%3};"
        : "+f"(c[0]), "+f"(c[1]), "+f"(c[2]), "+f"(c[3])
        : "r"(a[0]), "r"(a[1]), "r"(a[2]), "r"(a[3]), "r"(b[0]), "r"(b[1]));
}

// ---------------- conversion preprocessing ----------------
__global__ void k_conv_x(const float4* __restrict__ x4, size_t total4) {
    size_t i = (size_t)blockIdx.x * blockDim.x + threadIdx.x;
    if (i >= total4) return;
    float4 v = x4[i];
    __half2* p = reinterpret_cast<__half2*>(&g_xf[i * 4]);
    p[0] = __floats2half2_rn(v.x, v.y);
    p[1] = __floats2half2_rn(v.z, v.w);
}

template<int WMODE>
__global__ void k_conv_w(const float* __restrict__ W) {
    constexpr int KD   = (WMODE == 0) ? IN_CH : (WMODE == 1) ? KCAT : HID;
    constexpr int ND   = (WMODE == 0) ? G_CH  : (WMODE == 1) ? HID  : NCLS;
    constexpr int NPAD = (WMODE == 0) ? G_CH  : (WMODE == 1) ? HID  : 128;
    int idx = blockIdx.x * blockDim.x + threadIdx.x;
    if (idx >= NPAD * KD) return;
    int n = idx / KD, k = idx % KD;
    float v = (n < ND) ? __ldg(&W[(size_t)k * ND + n]) : 0.0f;
    if (WMODE == 0) g_wgf[idx] = __float2half_rn(v);
    if (WMODE == 1) g_whf[idx] = __float2half_rn(v);
    if (WMODE == 2) g_wcf[idx] = __float2half_rn(v);
}

// ---------------- pipelined fp16 tensor-core GEMM ----------------
#define RS 40
#define PLANE_B  10240
#define STAGE_B  20480
#define SMEM_DYN 40960

// AM: 0 = x (K=1280), 1 = [x|x1] (K=1408), 2 = h (K=512)
// BMODE: 0/1/2 = W_gcn/W_hid/W_cls
// CM: 0 -> Cp fp32, 1 -> g_xwf fp16.  HOUT: vectorized h + g_hf epilogue (Nout=512).
template<int AM, int BMODE, bool BIAS, bool RELU, bool HOUT, int CM>
__global__ void __launch_bounds__(256, 2)
tc_gemm(const float* __restrict__ bias, float* __restrict__ Cp, int M, int Nout)
{
    extern __shared__ __align__(16) char dsm[];
    const uint32_t base = smem_u32(dsm);

    const int tid  = threadIdx.x;
    const int wid  = tid >> 5;
    const int lane = tid & 31;
    const int wm = wid >> 2;
    const int wn = wid & 3;
    // HOUT (GEMM2): n-block is the FAST CTA index so A-tiles are L2-hot across n.
    const int m0 = (HOUT ? blockIdx.y : blockIdx.x) * 128;
    const int n0 = (HOUT ? blockIdx.x : blockIdx.y) * 128;

    float acc[4][4][4];
#pragma unroll
    for (int i = 0; i < 4; i++)
#pragma unroll
        for (int j = 0; j < 4; j++)
#pragma unroll
            for (int r = 0; r < 4; r++) acc[i][j][r] = 0.0f;

    constexpr int K  = (AM == 0) ? IN_CH : (AM == 1) ? KCAT : HID;
    constexpr int Kb = (BMODE == 0) ? IN_CH : (BMODE == 1) ? KCAT : HID;
    constexpr int nchunks = K >> 5;

    const int lrow = lane & 15;
    const int lko  = (lane >> 4) << 3;

    auto issue = [&](int ch, int stg) {
        const int k0 = ch << 5;
        const __half* pA; int Kd, koff;
        if (AM == 0) { pA = g_xf; Kd = IN_CH; koff = k0; }
        else if (AM == 2) { pA = g_hf; Kd = HID; koff = k0; }
        else {
            if (k0 < IN_CH) { pA = g_xf;  Kd = IN_CH; koff = k0; }
            else            { pA = g_x1f; Kd = G_CH;  koff = k0 - IN_CH; }
        }
        const __half* pB = (BMODE == 0) ? g_wgf : (BMODE == 1) ? g_whf : g_wcf;

        const uint32_t sb = base + stg * STAGE_B;
#pragma unroll
        for (int it = 0; it < 2; it++) {
            int o = tid + it * 256;
            int row = o >> 2, grp = o & 3;
            uint32_t so = (uint32_t)(row * (RS * 2) + grp * 16);
            cp16(sb + so,           pA + (size_t)(m0 + row) * Kd + koff + grp * 8);
            cp16(sb + PLANE_B + so, pB + (size_t)(n0 + row) * Kb + k0 + grp * 8);
        }
        asm volatile("cp.async.commit_group;");
    };

    issue(0, 0);
    for (int ch = 0; ch < nchunks; ch++) {
        const int stg = ch & 1;
        if (ch + 1 < nchunks) {
            issue(ch + 1, stg ^ 1);
            asm volatile("cp.async.wait_group 1;");
        } else {
            asm volatile("cp.async.wait_group 0;");
        }
        __syncthreads();

        const uint32_t uA = base + stg * STAGE_B;
        const uint32_t uB = uA + PLANE_B;

#pragma unroll
        for (int s = 0; s < 2; s++) {
            const int ks = s * 16 + lko;
            uint32_t bt[4][2];
#pragma unroll
            for (int g = 0; g < 2; g++) {
                uint32_t r[4];
                uint32_t addr = uB + ((wn * 32 + g * 16 + lrow) * RS + ks) * 2;
                ldm_x4(r, addr);
                bt[2 * g][0] = r[0]; bt[2 * g][1] = r[2];
                bt[2 * g + 1][0] = r[1]; bt[2 * g + 1][1] = r[3];
            }
            uint32_t at[4][4];
#pragma unroll
            for (int mt = 0; mt < 4; mt++) {
                uint32_t addr = uA + ((wm * 64 + mt * 16 + lrow) * RS + ks) * 2;
                ldm_x4(at[mt], addr);
            }
#pragma unroll
            for (int mt = 0; mt < 4; mt++)
#pragma unroll
                for (int nt = 0; nt < 4; nt++)
                    mma16816(acc[mt][nt], at[mt], bt[nt]);
        }
        __syncthreads();
    }

    // ---- epilogue ----
    const int qr = lane >> 2;
    const int qc = (lane & 3) * 2;
#pragma unroll
    for (int mt = 0; mt < 4; mt++) {
#pragma unroll
        for (int nt = 0; nt < 4; nt++) {
#pragma unroll
            for (int half = 0; half < 2; half++) {
                int gm = m0 + wm * 64 + mt * 16 + qr + half * 8;
                if (gm >= M) continue;
                int gn0 = n0 + wn * 32 + nt * 8 + qc;     // even
                float v0 = acc[mt][nt][half * 2 + 0];
                float v1 = acc[mt][nt][half * 2 + 1];
                if (BIAS) { v0 += __ldg(&bias[gn0]); v1 += __ldg(&bias[gn0 + 1]); }
                if (RELU) { v0 = fmaxf(v0, 0.0f); v1 = fmaxf(v1, 0.0f); }
                if (CM == 1) {
                    // GEMM1: fp16 xw plane (half2 aligned store)
                    *reinterpret_cast<__half2*>(&g_xwf[(size_t)gm * G_CH + gn0]) =
                        __floats2half2_rn(v0, v1);
                } else if (HOUT) {
                    // GEMM2: vectorized fp32 h + fp16 plane (Nout=512)
                    *reinterpret_cast<float2*>(&Cp[(size_t)gm * Nout + gn0]) =
                        make_float2(v0, v1);
                    *reinterpret_cast<__half2*>(&g_hf[(size_t)gm * HID + gn0]) =
                        __floats2half2_rn(v0, v1);
                } else {
                    // GEMM3: scalar guarded stores (Nout=79)
                    if (gn0 < Nout)     Cp[(size_t)gm * Nout + gn0]     = v0;
                    if (gn0 + 1 < Nout) Cp[(size_t)gm * Nout + gn0 + 1] = v1;
                }
            }
        }
    }
}

// ---------------- edge dtype probe ----------------
__global__ void k_detect(const void* ei_raw, int E, int n) {
    if (threadIdx.x == 0 && blockIdx.x == 0) {
        const long long* p = (const long long*)ei_raw;
        int bad = 0;
        int samples = E < 512 ? E : 512;
        for (int i = 0; i < samples; i++) {
            long long v = p[i];
            if (v < 0 || v >= n) { bad = 1; break; }
        }
        g_i64mode = bad ? 0 : 1;
    }
}
__device__ __forceinline__ int edge_at(const void* ei_raw, size_t idx) {
    if (g_i64mode) return (int)((const long long*)ei_raw)[idx];
    return ((const int*)ei_raw)[idx];
}

// ---------------- graph / elementwise kernels ----------------
__global__ void k_init_deg(int n) {
    int i = blockIdx.x * blockDim.x + threadIdx.x;
    if (i < n) g_deg[i] = 1.0f;
}
__global__ void k_deg(const void* __restrict__ ei, int E, int n) {
    int i = blockIdx.x * blockDim.x + threadIdx.x;
    if (i < E) {
        int t = edge_at(ei, (size_t)E + i);
        t = max(0, min(n - 1, t));
        atomicAdd(&g_deg[t], 1.0f);
    }
}
__global__ void k_dinv(int n) {
    int i = blockIdx.x * blockDim.x + threadIdx.x;
    if (i < n) g_deg[i] = rsqrtf(g_deg[i]);
}
__global__ void k_zero_agg(int total2) {   // zero g_aggh as uint32
    int i = blockIdx.x * blockDim.x + threadIdx.x;
    if (i < total2) reinterpret_cast<uint32_t*>(g_aggh)[i] = 0u;
}
// one warp per edge: aggh[col] += xwf[row] * (dinv_r*dinv_c), half2 atomics
__global__ void k_scatter(const void* __restrict__ ei, int E, int n) {
    int gw = (blockIdx.x * blockDim.x + threadIdx.x) >> 5;
    int lane = threadIdx.x & 31;
    if (gw >= E) return;
    int r = edge_at(ei, gw);
    int c = edge_at(ei, (size_t)E + gw);
    r = max(0, min(n - 1, r));
    c = max(0, min(n - 1, c));
    float w = g_deg[r] * g_deg[c];
    const __half2* src = reinterpret_cast<const __half2*>(g_xwf + (size_t)r * G_CH);
    __half2*       dst = reinterpret_cast<__half2*>(g_aggh + (size_t)c * G_CH);
#pragma unroll
    for (int j = 0; j < 2; j++) {
        float2 f = __half22float2(src[lane + 32 * j]);
        atomicAdd(&dst[lane + 32 * j], __floats2half2_rn(f.x * w, f.y * w));
    }
}
// x1 = relu(agg + xw*dinv^2 + b) -> fp16 plane (self-loop folded in)
__global__ void k_bias_relu_conv(const float* __restrict__ b, int total) {
    int i = blockIdx.x * blockDim.x + threadIdx.x;
    if (i < total) {
        float d = g_deg[i >> 7];
        float v = __half2float(g_aggh[i]) + __half2float(g_xwf[i]) * (d * d)
                + b[i & (G_CH - 1)];
        g_x1f[i] = __float2half_rn(fmaxf(v, 0.0f));
    }
}

// ---------------- launch ----------------
extern "C" void kernel_launch(void* const* d_in, const int* in_sizes, int n_in,
                              void* d_out, int out_size) {
    const float* x     = nullptr;  int x_cnt = 0;
    const void*  ei    = nullptr;  int ei_cnt = 0;
    const float* W_gcn = nullptr;
    const float* b_gcn = nullptr;
    const float* W_hid = nullptr;
    const float* b_hid = nullptr;
    const float* W_cls = nullptr;
    const float* b_cls = nullptr;

    int max_cnt = 0;
    for (int i = 0; i < n_in; i++) if (in_sizes[i] > max_cnt) max_cnt = in_sizes[i];
    for (int i = 0; i < n_in; i++) {
        int c = in_sizes[i];
        if      (c == IN_CH * G_CH)  W_gcn = (const float*)d_in[i];
        else if (c == KCAT * HID)    W_hid = (const float*)d_in[i];
        else if (c == HID * NCLS)    W_cls = (const float*)d_in[i];
        else if (c == G_CH)          b_gcn = (const float*)d_in[i];
        else if (c == HID)           b_hid = (const float*)d_in[i];
        else if (c == NCLS)          b_cls = (const float*)d_in[i];
        else if (c == max_cnt && c % IN_CH == 0) { x = (const float*)d_in[i]; x_cnt = c; }
    }
    const int N = x_cnt / IN_CH;

    for (int i = 0; i < n_in; i++) {
        const void* p = d_in[i];
        if (p == (const void*)x || p == (const void*)W_gcn || p == (const void*)W_hid ||
            p == (const void*)W_cls || p == (const void*)b_gcn || p == (const void*)b_hid ||
            p == (const void*)b_cls) continue;
        int c = in_sizes[i];
        if (c != 2 * N) { ei = p; ei_cnt = c; }
        else if (ei == nullptr) { ei = p; ei_cnt = c; }
    }
    const int E = ei_cnt / 2;

    float* h      = (float*)d_out;
    float* logits = h + (size_t)N * HID;

    const int mblocks = (N + 127) / 128;

    // 0) probes + fp16 conversions + agg zero
    k_detect<<<1, 32>>>(ei, E, N);
    size_t total4 = (size_t)N * IN_CH / 4;
    k_conv_x<<<(unsigned)((total4 + 255) / 256), 256>>>((const float4*)x, total4);
    k_conv_w<0><<<(G_CH * IN_CH + 255) / 256, 256>>>(W_gcn);
    k_conv_w<1><<<(HID * KCAT + 255) / 256, 256>>>(W_hid);
    k_conv_w<2><<<(128 * HID + 255) / 256, 256>>>(W_cls);
    int tot2 = N * G_CH / 2;
    k_zero_agg<<<(tot2 + 255) / 256, 256>>>(tot2);

    // 1) xw = x @ W_gcn -> g_xwf (fp16)
    tc_gemm<0, 0, false, false, false, 1><<<dim3(mblocks, 1), 256, SMEM_DYN>>>(nullptr, nullptr, N, G_CH);

    // 2) degree + dinv
    k_init_deg<<<(N + 255) / 256, 256>>>(N);
    k_deg<<<(E + 255) / 256, 256>>>(ei, E, N);
    k_dinv<<<(N + 255) / 256, 256>>>(N);

    // 3) edge scatter (half2 atomics) + fused self-loop/bias/relu -> x1 fp16
    k_scatter<<<(E + 7) / 8, 256>>>(ei, E, N);
    int tot = N * G_CH;
    k_bias_relu_conv<<<(tot + 255) / 256, 256>>>(b_gcn, tot);

    // 4) h = relu([x | x1] @ W_hid + b_hid) -> d_out (+ fp16 plane); n-fast grid
    tc_gemm<1, 1, true, true, true, 0><<<dim3(4, mblocks), 256, SMEM_DYN>>>(b_hid, h, N, HID);

    // 5) logits = h @ W_cls + b_cls
    tc_gemm<2, 2, true, false, false, 0><<<dim3(mblocks, 1), 256, SMEM_DYN>>>(b_cls, logits, N, NCLS);
}

// round 12
// speedup vs baseline: 9.2346x; 1.1318x over previous
#include <cuda_runtime.h>
#include <cuda_fp16.h>
#include <cstdint>

#define N_NODES 100000
#define N_PAD   100096
#define E_MAX   700000
#define IN_CH   1280
#define G_CH    128
#define HID     512
#define NCLS    79
#define KCAT    (IN_CH + G_CH)
#define SCAN_B  512

// ---------------- scratch (device globals; no allocation allowed) ----------------
__device__ float  g_dinv[N_NODES];
__device__ int    g_cnt [N_NODES];
__device__ int    g_offs[N_NODES + 1];
__device__ int    g_cur [N_NODES];
__device__ int    g_bsum[256];
__device__ int    g_esrc[E_MAX];
__device__ int    g_i64mode;
__device__ __half g_xwf[(size_t)N_PAD * G_CH];    // x @ W_gcn (fp16)
__device__ __half g_xf [(size_t)N_PAD * IN_CH];
__device__ __half g_x1f[(size_t)N_PAD * G_CH];
__device__ __half g_hf [(size_t)N_PAD * HID];
__device__ __half g_wgf[G_CH * IN_CH];
__device__ __half g_whf[HID * KCAT];
__device__ __half g_wcf[128 * HID];

// ---------------- PTX helpers ----------------
__device__ __forceinline__ uint32_t smem_u32(const void* p) {
    uint32_t a;
    asm("{ .reg .u64 t; cvta.to.shared.u64 t, %1; cvt.u32.u64 %0, t; }" : "=r"(a) : "l"(p));
    return a;
}
__device__ __forceinline__ void cp16(uint32_t dst, const void* src) {
    asm volatile("cp.async.cg.shared.global [%0], [%1], 16;" :: "r"(dst), "l"(src));
}
__device__ __forceinline__ void ldm_x4(uint32_t* r, uint32_t addr) {
    asm volatile("ldmatrix.sync.aligned.m8n8.x4.shared.b16 {%0,%1,%2,%3}, [%4];"
        : "=r"(r[0]), "=r"(r[1]), "=r"(r[2]), "=r"(r[3]) : "r"(addr));
}
__device__ __forceinline__ void mma16816(float* c, const uint32_t* a, const uint32_t* b) {
    asm volatile("mma.sync.aligned.m16n8k16.row.col.f32.f16.f16.f32 "
        "{%0,%1,%2,%3}, {%4,%5,%6,%7}, {%8,%9}, {%0,%1,%2,%3};"
        : "+f"(c[0]), "+f"(c[1]), "+f"(c[2]), "+f"(c[3])
        : "r"(a[0]), "r"(a[1]), "r"(a[2]), "r"(a[3]), "r"(b[0]), "r"(b[1]));
}

// ---------------- conversion preprocessing ----------------
__global__ void k_conv_x(const float4* __restrict__ x4, size_t total4) {
    size_t i = (size_t)blockIdx.x * blockDim.x + threadIdx.x;
    if (i >= total4) return;
    float4 v = x4[i];
    __half2* p = reinterpret_cast<__half2*>(&g_xf[i * 4]);
    p[0] = __floats2half2_rn(v.x, v.y);
    p[1] = __floats2half2_rn(v.z, v.w);
}

template<int WMODE>
__global__ void k_conv_w(const float* __restrict__ W) {
    constexpr int KD   = (WMODE == 0) ? IN_CH : (WMODE == 1) ? KCAT : HID;
    constexpr int ND   = (WMODE == 0) ? G_CH  : (WMODE == 1) ? HID  : NCLS;
    constexpr int NPAD = (WMODE == 0) ? G_CH  : (WMODE == 1) ? HID  : 128;
    int idx = blockIdx.x * blockDim.x + threadIdx.x;
    if (idx >= NPAD * KD) return;
    int n = idx / KD, k = idx % KD;
    float v = (n < ND) ? __ldg(&W[(size_t)k * ND + n]) : 0.0f;
    if (WMODE == 0) g_wgf[idx] = __float2half_rn(v);
    if (WMODE == 1) g_whf[idx] = __float2half_rn(v);
    if (WMODE == 2) g_wcf[idx] = __float2half_rn(v);
}

// ---------------- pipelined fp16 tensor-core GEMM ----------------
#define RS 40
#define PLANE_B  10240
#define STAGE_B  20480
#define SMEM_DYN 40960

template<int AM, int BMODE, bool BIAS, bool RELU, bool HOUT, int CM>
__global__ void __launch_bounds__(256, 2)
tc_gemm(const float* __restrict__ bias, float* __restrict__ Cp, int M, int Nout)
{
    extern __shared__ __align__(16) char dsm[];
    const uint32_t base = smem_u32(dsm);

    const int tid  = threadIdx.x;
    const int wid  = tid >> 5;
    const int lane = tid & 31;
    const int wm = wid >> 2;
    const int wn = wid & 3;
    const int m0 = (HOUT ? blockIdx.y : blockIdx.x) * 128;
    const int n0 = (HOUT ? blockIdx.x : blockIdx.y) * 128;

    float acc[4][4][4];
#pragma unroll
    for (int i = 0; i < 4; i++)
#pragma unroll
        for (int j = 0; j < 4; j++)
#pragma unroll
            for (int r = 0; r < 4; r++) acc[i][j][r] = 0.0f;

    constexpr int K  = (AM == 0) ? IN_CH : (AM == 1) ? KCAT : HID;
    constexpr int Kb = (BMODE == 0) ? IN_CH : (BMODE == 1) ? KCAT : HID;
    constexpr int nchunks = K >> 5;

    const int lrow = lane & 15;
    const int lko  = (lane >> 4) << 3;

    auto issue = [&](int ch, int stg) {
        const int k0 = ch << 5;
        const __half* pA; int Kd, koff;
        if (AM == 0) { pA = g_xf; Kd = IN_CH; koff = k0; }
        else if (AM == 2) { pA = g_hf; Kd = HID; koff = k0; }
        else {
            if (k0 < IN_CH) { pA = g_xf;  Kd = IN_CH; koff = k0; }
            else            { pA = g_x1f; Kd = G_CH;  koff = k0 - IN_CH; }
        }
        const __half* pB = (BMODE == 0) ? g_wgf : (BMODE == 1) ? g_whf : g_wcf;

        const uint32_t sb = base + stg * STAGE_B;
#pragma unroll
        for (int it = 0; it < 2; it++) {
            int o = tid + it * 256;
            int row = o >> 2, grp = o & 3;
            uint32_t so = (uint32_t)(row * (RS * 2) + grp * 16);
            cp16(sb + so,           pA + (size_t)(m0 + row) * Kd + koff + grp * 8);
            cp16(sb + PLANE_B + so, pB + (size_t)(n0 + row) * Kb + k0 + grp * 8);
        }
        asm volatile("cp.async.commit_group;");
    };

    issue(0, 0);
    for (int ch = 0; ch < nchunks; ch++) {
        const int stg = ch & 1;
        if (ch + 1 < nchunks) {
            issue(ch + 1, stg ^ 1);
            asm volatile("cp.async.wait_group 1;");
        } else {
            asm volatile("cp.async.wait_group 0;");
        }
        __syncthreads();

        const uint32_t uA = base + stg * STAGE_B;
        const uint32_t uB = uA + PLANE_B;

#pragma unroll
        for (int s = 0; s < 2; s++) {
            const int ks = s * 16 + lko;
            uint32_t bt[4][2];
#pragma unroll
            for (int g = 0; g < 2; g++) {
                uint32_t r[4];
                uint32_t addr = uB + ((wn * 32 + g * 16 + lrow) * RS + ks) * 2;
                ldm_x4(r, addr);
                bt[2 * g][0] = r[0]; bt[2 * g][1] = r[2];
                bt[2 * g + 1][0] = r[1]; bt[2 * g + 1][1] = r[3];
            }
            uint32_t at[4][4];
#pragma unroll
            for (int mt = 0; mt < 4; mt++) {
                uint32_t addr = uA + ((wm * 64 + mt * 16 + lrow) * RS + ks) * 2;
                ldm_x4(at[mt], addr);
            }
#pragma unroll
            for (int mt = 0; mt < 4; mt++)
#pragma unroll
                for (int nt = 0; nt < 4; nt++)
                    mma16816(acc[mt][nt], at[mt], bt[nt]);
        }
        __syncthreads();
    }

    const int qr = lane >> 2;
    const int qc = (lane & 3) * 2;
#pragma unroll
    for (int mt = 0; mt < 4; mt++) {
#pragma unroll
        for (int nt = 0; nt < 4; nt++) {
#pragma unroll
            for (int half = 0; half < 2; half++) {
                int gm = m0 + wm * 64 + mt * 16 + qr + half * 8;
                if (gm >= M) continue;
                int gn0 = n0 + wn * 32 + nt * 8 + qc;
                float v0 = acc[mt][nt][half * 2 + 0];
                float v1 = acc[mt][nt][half * 2 + 1];
                if (BIAS) { v0 += __ldg(&bias[gn0]); v1 += __ldg(&bias[gn0 + 1]); }
                if (RELU) { v0 = fmaxf(v0, 0.0f); v1 = fmaxf(v1, 0.0f); }
                if (CM == 1) {
                    *reinterpret_cast<__half2*>(&g_xwf[(size_t)gm * G_CH + gn0]) =
                        __floats2half2_rn(v0, v1);
                } else if (HOUT) {
                    *reinterpret_cast<float2*>(&Cp[(size_t)gm * Nout + gn0]) =
                        make_float2(v0, v1);
                    *reinterpret_cast<__half2*>(&g_hf[(size_t)gm * HID + gn0]) =
                        __floats2half2_rn(v0, v1);
                } else {
                    if (gn0 < Nout)     Cp[(size_t)gm * Nout + gn0]     = v0;
                    if (gn0 + 1 < Nout) Cp[(size_t)gm * Nout + gn0 + 1] = v1;
                }
            }
        }
    }
}

// ---------------- edge dtype probe ----------------
__global__ void k_detect(const void* ei_raw, int E, int n) {
    if (threadIdx.x == 0 && blockIdx.x == 0) {
        const long long* p = (const long long*)ei_raw;
        int bad = 0;
        int samples = E < 512 ? E : 512;
        for (int i = 0; i < samples; i++) {
            long long v = p[i];
            if (v < 0 || v >= n) { bad = 1; break; }
        }
        g_i64mode = bad ? 0 : 1;
    }
}
__device__ __forceinline__ int edge_at(const void* ei_raw, size_t idx) {
    if (g_i64mode) return (int)((const long long*)ei_raw)[idx];
    return ((const int*)ei_raw)[idx];
}

// ---------------- CSR build ----------------
__global__ void k_zero_cnt(int n) {
    int i = blockIdx.x * blockDim.x + threadIdx.x;
    if (i < n) g_cnt[i] = 0;
}
__global__ void k_count(const void* __restrict__ ei, int E, int n) {
    int i = blockIdx.x * blockDim.x + threadIdx.x;
    if (i < E) {
        int t = edge_at(ei, (size_t)E + i);
        t = max(0, min(n - 1, t));
        atomicAdd(&g_cnt[t], 1);
    }
}
__global__ void k_dinv(int n) {
    int i = blockIdx.x * blockDim.x + threadIdx.x;
    if (i < n) g_dinv[i] = rsqrtf((float)(g_cnt[i] + 1));   // +1 self-loop
}
// block-local exclusive scan (Hillis-Steele), per-block totals to g_bsum
__global__ void k_scan1(int n) {
    __shared__ int s[SCAN_B];
    int i = blockIdx.x * SCAN_B + threadIdx.x;
    int v = (i < n) ? g_cnt[i] : 0;
    s[threadIdx.x] = v;
    __syncthreads();
#pragma unroll
    for (int d = 1; d < SCAN_B; d <<= 1) {
        int t = (threadIdx.x >= d) ? s[threadIdx.x - d] : 0;
        __syncthreads();
        s[threadIdx.x] += t;
        __syncthreads();
    }
    if (i < n) g_offs[i] = s[threadIdx.x] - v;              // exclusive
    if (threadIdx.x == SCAN_B - 1) g_bsum[blockIdx.x] = s[threadIdx.x];
}
// exclusive scan of <=256 block sums, single block
__global__ void k_scan2(int nb) {
    __shared__ int s[256];
    int v = (threadIdx.x < nb) ? g_bsum[threadIdx.x] : 0;
    s[threadIdx.x] = v;
    __syncthreads();
#pragma unroll
    for (int d = 1; d < 256; d <<= 1) {
        int t = (threadIdx.x >= d) ? s[threadIdx.x - d] : 0;
        __syncthreads();
        s[threadIdx.x] += t;
        __syncthreads();
    }
    if (threadIdx.x < nb) g_bsum[threadIdx.x] = s[threadIdx.x] - v;
}
__global__ void k_scan3(int n, int E) {
    int i = blockIdx.x * blockDim.x + threadIdx.x;
    if (i < n) {
        int o = g_offs[i] + g_bsum[i / SCAN_B];
        g_offs[i] = o;
        g_cur[i]  = o;
    }
    if (i == 0) g_offs[n] = E;
}
__global__ void k_fill(const void* __restrict__ ei, int E, int n) {
    int e = blockIdx.x * blockDim.x + threadIdx.x;
    if (e >= E) return;
    int r = edge_at(ei, e);
    int c = edge_at(ei, (size_t)E + e);
    r = max(0, min(n - 1, r));
    c = max(0, min(n - 1, c));
    int pos = atomicAdd(&g_cur[c], 1);
    g_esrc[pos] = r;
}

// ---------------- warp-per-node gather: x1 = relu(sum + self + bias) ----------------
__global__ void k_gather(const float* __restrict__ b, int n) {
    int node = (blockIdx.x * blockDim.x + threadIdx.x) >> 5;
    int lane = threadIdx.x & 31;
    if (node >= n) return;
    const float dc = g_dinv[node];
    const int beg = g_offs[node], end = g_offs[node + 1];

    // self-loop term
    const __half2* selfrow = reinterpret_cast<const __half2*>(g_xwf + (size_t)node * G_CH);
    float2 s0 = __half22float2(selfrow[lane]);
    float2 s1 = __half22float2(selfrow[lane + 32]);
    float ws = dc * dc;
    float a0 = s0.x * ws, a1 = s0.y * ws, a2 = s1.x * ws, a3 = s1.y * ws;

    for (int e = beg; e < end; e++) {
        int r = g_esrc[e];
        float w = g_dinv[r] * dc;
        const __half2* src = reinterpret_cast<const __half2*>(g_xwf + (size_t)r * G_CH);
        float2 f0 = __half22float2(src[lane]);
        float2 f1 = __half22float2(src[lane + 32]);
        a0 = fmaf(f0.x, w, a0); a1 = fmaf(f0.y, w, a1);
        a2 = fmaf(f1.x, w, a2); a3 = fmaf(f1.y, w, a3);
    }
    int c0 = 2 * lane, c1 = 2 * (lane + 32);
    a0 = fmaxf(a0 + __ldg(&b[c0]),     0.0f);
    a1 = fmaxf(a1 + __ldg(&b[c0 + 1]), 0.0f);
    a2 = fmaxf(a2 + __ldg(&b[c1]),     0.0f);
    a3 = fmaxf(a3 + __ldg(&b[c1 + 1]), 0.0f);
    __half2* dst = reinterpret_cast<__half2*>(g_x1f + (size_t)node * G_CH);
    dst[lane]      = __floats2half2_rn(a0, a1);
    dst[lane + 32] = __floats2half2_rn(a2, a3);
}

// ---------------- launch ----------------
extern "C" void kernel_launch(void* const* d_in, const int* in_sizes, int n_in,
                              void* d_out, int out_size) {
    const float* x     = nullptr;  int x_cnt = 0;
    const void*  ei    = nullptr;  int ei_cnt = 0;
    const float* W_gcn = nullptr;
    const float* b_gcn = nullptr;
    const float* W_hid = nullptr;
    const float* b_hid = nullptr;
    const float* W_cls = nullptr;
    const float* b_cls = nullptr;

    int max_cnt = 0;
    for (int i = 0; i < n_in; i++) if (in_sizes[i] > max_cnt) max_cnt = in_sizes[i];
    for (int i = 0; i < n_in; i++) {
        int c = in_sizes[i];
        if      (c == IN_CH * G_CH)  W_gcn = (const float*)d_in[i];
        else if (c == KCAT * HID)    W_hid = (const float*)d_in[i];
        else if (c == HID * NCLS)    W_cls = (const float*)d_in[i];
        else if (c == G_CH)          b_gcn = (const float*)d_in[i];
        else if (c == HID)           b_hid = (const float*)d_in[i];
        else if (c == NCLS)          b_cls = (const float*)d_in[i];
        else if (c == max_cnt && c % IN_CH == 0) { x = (const float*)d_in[i]; x_cnt = c; }
    }
    const int N = x_cnt / IN_CH;

    for (int i = 0; i < n_in; i++) {
        const void* p = d_in[i];
        if (p == (const void*)x || p == (const void*)W_gcn || p == (const void*)W_hid ||
            p == (const void*)W_cls || p == (const void*)b_gcn || p == (const void*)b_hid ||
            p == (const void*)b_cls) continue;
        int c = in_sizes[i];
        if (c != 2 * N) { ei = p; ei_cnt = c; }
        else if (ei == nullptr) { ei = p; ei_cnt = c; }
    }
    const int E = ei_cnt / 2;

    float* h      = (float*)d_out;
    float* logits = h + (size_t)N * HID;

    const int mblocks = (N + 127) / 128;
    const int nscan   = (N + SCAN_B - 1) / SCAN_B;

    // 0) probes + fp16 conversions
    k_detect<<<1, 32>>>(ei, E, N);
    size_t total4 = (size_t)N * IN_CH / 4;
    k_conv_x<<<(unsigned)((total4 + 255) / 256), 256>>>((const float4*)x, total4);
    k_conv_w<0><<<(G_CH * IN_CH + 255) / 256, 256>>>(W_gcn);
    k_conv_w<1><<<(HID * KCAT + 255) / 256, 256>>>(W_hid);
    k_conv_w<2><<<(128 * HID + 255) / 256, 256>>>(W_cls);

    // 1) xw = x @ W_gcn -> g_xwf (fp16)
    tc_gemm<0, 0, false, false, false, 1><<<dim3(mblocks, 1), 256, SMEM_DYN>>>(nullptr, nullptr, N, G_CH);

    // 2) CSR build: count -> dinv -> scan -> fill
    k_zero_cnt<<<(N + 255) / 256, 256>>>(N);
    k_count<<<(E + 255) / 256, 256>>>(ei, E, N);
    k_dinv<<<(N + 255) / 256, 256>>>(N);
    k_scan1<<<nscan, SCAN_B>>>(N);
    k_scan2<<<1, 256>>>(nscan);
    k_scan3<<<(N + 255) / 256, 256>>>(N, E);
    k_fill<<<(E + 255) / 256, 256>>>(ei, E, N);

    // 3) gather-aggregate (+self+bias+relu) -> x1 fp16
    k_gather<<<(N * 32 + 255) / 256, 256>>>(b_gcn, N);

    // 4) h = relu([x | x1] @ W_hid + b_hid) -> d_out (+ fp16 plane); n-fast grid
    tc_gemm<1, 1, true, true, true, 0><<<dim3(4, mblocks), 256, SMEM_DYN>>>(b_hid, h, N, HID);

    // 5) logits = h @ W_cls + b_cls
    tc_gemm<2, 2, true, false, false, 0><<<dim3(mblocks, 1), 256, SMEM_DYN>>>(b_cls, logits, N, NCLS);
}

// round 14
// speedup vs baseline: 9.9803x; 1.0808x over previous
#include <cuda_runtime.h>
#include <cuda_fp16.h>
#include <cstdint>

#define N_NODES 100000
#define N_PAD   100096
#define E_MAX   700000
#define IN_CH   1280
#define G_CH    128
#define HID     512
#define NCLS    79
#define KCAT    (IN_CH + G_CH)
#define SCAN_B  512

// ---------------- scratch (device globals; no allocation allowed) ----------------
__device__ float  g_dinv[N_NODES];
__device__ int    g_cnt [N_NODES];
__device__ int    g_offs[N_NODES + 1];
__device__ int    g_cur [N_NODES];
__device__ int    g_bsum[256];
__device__ int    g_esrc[E_MAX];
__device__ int    g_i64mode;
__device__ __half g_xwf[(size_t)N_PAD * G_CH];    // x @ W_gcn (fp16)
__device__ __half g_xf [(size_t)N_PAD * IN_CH];   // fp16 x (written by fused GEMM1)
__device__ __half g_x1f[(size_t)N_PAD * G_CH];
__device__ __half g_hf [(size_t)N_PAD * HID];
__device__ __half g_wgf[G_CH * IN_CH];
__device__ __half g_whf[HID * KCAT];
__device__ __half g_wcf[128 * HID];

// ---------------- PTX helpers ----------------
__device__ __forceinline__ uint32_t smem_u32(const void* p) {
    uint32_t a;
    asm("{ .reg .u64 t; cvta.to.shared.u64 t, %1; cvt.u32.u64 %0, t; }" : "=r"(a) : "l"(p));
    return a;
}
__device__ __forceinline__ void cp16(uint32_t dst, const void* src) {
    asm volatile("cp.async.cg.shared.global [%0], [%1], 16;" :: "r"(dst), "l"(src));
}
__device__ __forceinline__ void ldm_x4(uint32_t* r, uint32_t addr) {
    asm volatile("ldmatrix.sync.aligned.m8n8.x4.shared.b16 {%0,%1,%2,%3}, [%4];"
        : "=r"(r[0]), "=r"(r[1]), "=r"(r[2]), "=r"(r[3]) : "r"(addr));
}
__device__ __forceinline__ void mma16816(float* c, const uint32_t* a, const uint32_t* b) {
    asm volatile("mma.sync.aligned.m16n8k16.row.col.f32.f16.f16.f32 "
        "{%0,%1,%2,%3}, {%4,%5,%6,%7}, {%8,%9}, {%0,%1,%2,%3};"
        : "+f"(c[0]), "+f"(c[1]), "+f"(c[2]), "+f"(c[3])
        : "r"(a[0]), "r"(a[1]), "r"(a[2]), "r"(a[3]), "r"(b[0]), "r"(b[1]));
}
__device__ __forceinline__ void sts16(uint32_t addr, uint32_t a, uint32_t b, uint32_t c, uint32_t d) {
    asm volatile("st.shared.v4.b32 [%0], {%1,%2,%3,%4};" :: "r"(addr), "r"(a), "r"(b), "r"(c), "r"(d));
}
__device__ __forceinline__ uint32_t h2u(__half2 h) {
    return *reinterpret_cast<uint32_t*>(&h);
}
__device__ __forceinline__ uint32_t pack2(float a, float b) {
    return h2u(__floats2half2_rn(a, b));
}

// ---------------- weight conversion ----------------
template<int WMODE>
__global__ void k_conv_w(const float* __restrict__ W) {
    constexpr int KD   = (WMODE == 0) ? IN_CH : (WMODE == 1) ? KCAT : HID;
    constexpr int ND   = (WMODE == 0) ? G_CH  : (WMODE == 1) ? HID  : NCLS;
    constexpr int NPAD = (WMODE == 0) ? G_CH  : (WMODE == 1) ? HID  : 128;
    int idx = blockIdx.x * blockDim.x + threadIdx.x;
    if (idx >= NPAD * KD) return;
    int n = idx / KD, k = idx % KD;
    float v = (n < ND) ? __ldg(&W[(size_t)k * ND + n]) : 0.0f;
    if (WMODE == 0) g_wgf[idx] = __float2half_rn(v);
    if (WMODE == 1) g_whf[idx] = __float2half_rn(v);
    if (WMODE == 2) g_wcf[idx] = __float2half_rn(v);
}

// ---------------- pipelined fp16 tensor-core GEMM ----------------
#define RS 40
#define PLANE_B  10240
#define STAGE_B  20480
#define SMEM_DYN 40960

// AFUSE: A read as fp32 from Afp32 (register double-buffer), converted, stored to
//        smem AND g_xf.  Otherwise A via cp.async from fp16 planes.
// AM: 0 = x (K=1280), 1 = [x|x1] (K=1408), 2 = h (K=512)
// BMODE: 0/1/2 = W_gcn/W_hid/W_cls.  CM: 0 -> Cp fp32, 1 -> g_xwf fp16.
// HOUT: vectorized h + g_hf epilogue (n-fast grid).
template<bool AFUSE, int AM, int BMODE, bool BIAS, bool RELU, bool HOUT, int CM>
__global__ void __launch_bounds__(256, 2)
tc_gemm(const float* __restrict__ Afp32, const float* __restrict__ bias,
        float* __restrict__ Cp, int M, int Nout)
{
    extern __shared__ __align__(16) char dsm[];
    const uint32_t base = smem_u32(dsm);

    const int tid  = threadIdx.x;
    const int wid  = tid >> 5;
    const int lane = tid & 31;
    const int wm = wid >> 2;
    const int wn = wid & 3;
    const int m0 = (HOUT ? blockIdx.y : blockIdx.x) * 128;
    const int n0 = (HOUT ? blockIdx.x : blockIdx.y) * 128;

    float acc[4][4][4];
#pragma unroll
    for (int i = 0; i < 4; i++)
#pragma unroll
        for (int j = 0; j < 4; j++)
#pragma unroll
            for (int r = 0; r < 4; r++) acc[i][j][r] = 0.0f;

    constexpr int K  = (AM == 0) ? IN_CH : (AM == 1) ? KCAT : HID;
    constexpr int Kb = (BMODE == 0) ? IN_CH : (BMODE == 1) ? KCAT : HID;
    constexpr int nchunks = K >> 5;

    const int lrow = lane & 15;
    const int lko  = (lane >> 4) << 3;

    // ---- B loader (always cp.async) ----
    auto issueB = [&](int ch, int stg) {
        const int k0 = ch << 5;
        const __half* pB = (BMODE == 0) ? g_wgf : (BMODE == 1) ? g_whf : g_wcf;
        const uint32_t sb = base + stg * STAGE_B + PLANE_B;
#pragma unroll
        for (int it = 0; it < 2; it++) {
            int o = tid + it * 256;
            int row = o >> 2, grp = o & 3;
            cp16(sb + (uint32_t)(row * (RS * 2) + grp * 16),
                 pB + (size_t)(n0 + row) * Kb + k0 + grp * 8);
        }
    };
    // ---- A loader, fp16 plane path ----
    auto issueA = [&](int ch, int stg) {
        const int k0 = ch << 5;
        const __half* pA; int Kd, koff;
        if (AM == 0) { pA = g_xf; Kd = IN_CH; koff = k0; }
        else if (AM == 2) { pA = g_hf; Kd = HID; koff = k0; }
        else {
            if (k0 < IN_CH) { pA = g_xf;  Kd = IN_CH; koff = k0; }
            else            { pA = g_x1f; Kd = G_CH;  koff = k0 - IN_CH; }
        }
        const uint32_t sb = base + stg * STAGE_B;
#pragma unroll
        for (int it = 0; it < 2; it++) {
            int o = tid + it * 256;
            int row = o >> 2, grp = o & 3;
            cp16(sb + (uint32_t)(row * (RS * 2) + grp * 16),
                 pA + (size_t)(m0 + row) * Kd + koff + grp * 8);
        }
    };
    // ---- A loader, fused fp32 path: regs hold one chunk (2 it x 2 float4) ----
    float4 ra[2][2];
    auto loadA = [&](int ch) {
        const int k0 = ch << 5;
#pragma unroll
        for (int it = 0; it < 2; it++) {
            int o = tid + it * 256;
            int row = o >> 2, grp = o & 3;
            int gm = m0 + row;
            if (gm < M) {
                const float4* p = reinterpret_cast<const float4*>(
                    Afp32 + (size_t)gm * IN_CH + k0 + grp * 8);
                ra[it][0] = p[0];
                ra[it][1] = p[1];
            } else {
                ra[it][0] = make_float4(0.f, 0.f, 0.f, 0.f);
                ra[it][1] = make_float4(0.f, 0.f, 0.f, 0.f);
            }
        }
    };
    auto storeA = [&](int ch, int stg) {
        const int k0 = ch << 5;
        const uint32_t sb = base + stg * STAGE_B;
#pragma unroll
        for (int it = 0; it < 2; it++) {
            int o = tid + it * 256;
            int row = o >> 2, grp = o & 3;
            uint32_t h0 = pack2(ra[it][0].x, ra[it][0].y);
            uint32_t h1 = pack2(ra[it][0].z, ra[it][0].w);
            uint32_t h2 = pack2(ra[it][1].x, ra[it][1].y);
            uint32_t h3 = pack2(ra[it][1].z, ra[it][1].w);
            sts16(sb + (uint32_t)(row * (RS * 2) + grp * 16), h0, h1, h2, h3);
            // mirror to g_xf for GEMM2 (rows m0..m0+127 < N_PAD always)
            uint4* dst = reinterpret_cast<uint4*>(
                g_xf + (size_t)(m0 + row) * IN_CH + k0 + grp * 8);
            *dst = make_uint4(h0, h1, h2, h3);
        }
    };

    // ---- prologue ----
    if (AFUSE) {
        loadA(0);
        issueB(0, 0);
        asm volatile("cp.async.commit_group;");
        storeA(0, 0);
        asm volatile("cp.async.wait_group 0;");
        __syncthreads();
    } else {
        issueA(0, 0); issueB(0, 0);
        asm volatile("cp.async.commit_group;");
    }

    for (int ch = 0; ch < nchunks; ch++) {
        const int stg = ch & 1;
        if (AFUSE) {
            if (ch + 1 < nchunks) { loadA(ch + 1); issueB(ch + 1, stg ^ 1);
                                    asm volatile("cp.async.commit_group;"); }
        } else {
            if (ch + 1 < nchunks) {
                issueA(ch + 1, stg ^ 1); issueB(ch + 1, stg ^ 1);
                asm volatile("cp.async.commit_group;");
                asm volatile("cp.async.wait_group 1;");
            } else {
                asm volatile("cp.async.wait_group 0;");
            }
            __syncthreads();
        }

        const uint32_t uA = base + stg * STAGE_B;
        const uint32_t uB = uA + PLANE_B;

#pragma unroll
        for (int s = 0; s < 2; s++) {
            const int ks = s * 16 + lko;
            uint32_t bt[4][2];
#pragma unroll
            for (int g = 0; g < 2; g++) {
                uint32_t r[4];
                uint32_t addr = uB + ((wn * 32 + g * 16 + lrow) * RS + ks) * 2;
                ldm_x4(r, addr);
                bt[2 * g][0] = r[0]; bt[2 * g][1] = r[2];
                bt[2 * g + 1][0] = r[1]; bt[2 * g + 1][1] = r[3];
            }
            uint32_t at[4][4];
#pragma unroll
            for (int mt = 0; mt < 4; mt++) {
                uint32_t addr = uA + ((wm * 64 + mt * 16 + lrow) * RS + ks) * 2;
                ldm_x4(at[mt], addr);
            }
#pragma unroll
            for (int mt = 0; mt < 4; mt++)
#pragma unroll
                for (int nt = 0; nt < 4; nt++)
                    mma16816(acc[mt][nt], at[mt], bt[nt]);
        }

        if (AFUSE) {
            if (ch + 1 < nchunks) {
                storeA(ch + 1, stg ^ 1);
                asm volatile("cp.async.wait_group 0;");
            }
            __syncthreads();
        } else {
            __syncthreads();
        }
    }

    // ---- epilogue ----
    const int qr = lane >> 2;
    const int qc = (lane & 3) * 2;
#pragma unroll
    for (int mt = 0; mt < 4; mt++) {
#pragma unroll
        for (int nt = 0; nt < 4; nt++) {
#pragma unroll
            for (int half = 0; half < 2; half++) {
                int gm = m0 + wm * 64 + mt * 16 + qr + half * 8;
                if (gm >= M) continue;
                int gn0 = n0 + wn * 32 + nt * 8 + qc;
                float v0 = acc[mt][nt][half * 2 + 0];
                float v1 = acc[mt][nt][half * 2 + 1];
                if (BIAS) { v0 += __ldg(&bias[gn0]); v1 += __ldg(&bias[gn0 + 1]); }
                if (RELU) { v0 = fmaxf(v0, 0.0f); v1 = fmaxf(v1, 0.0f); }
                if (CM == 1) {
                    *reinterpret_cast<__half2*>(&g_xwf[(size_t)gm * G_CH + gn0]) =
                        __floats2half2_rn(v0, v1);
                } else if (HOUT) {
                    *reinterpret_cast<float2*>(&Cp[(size_t)gm * Nout + gn0]) =
                        make_float2(v0, v1);
                    *reinterpret_cast<__half2*>(&g_hf[(size_t)gm * HID + gn0]) =
                        __floats2half2_rn(v0, v1);
                } else {
                    if (gn0 < Nout)     Cp[(size_t)gm * Nout + gn0]     = v0;
                    if (gn0 + 1 < Nout) Cp[(size_t)gm * Nout + gn0 + 1] = v1;
                }
            }
        }
    }
}

// ---------------- edge dtype probe ----------------
__global__ void k_detect(const void* ei_raw, int E, int n) {
    if (threadIdx.x == 0 && blockIdx.x == 0) {
        const long long* p = (const long long*)ei_raw;
        int bad = 0;
        int samples = E < 512 ? E : 512;
        for (int i = 0; i < samples; i++) {
            long long v = p[i];
            if (v < 0 || v >= n) { bad = 1; break; }
        }
        g_i64mode = bad ? 0 : 1;
    }
}
__device__ __forceinline__ int edge_at(const void* ei_raw, size_t idx) {
    if (g_i64mode) return (int)((const long long*)ei_raw)[idx];
    return ((const int*)ei_raw)[idx];
}

// ---------------- CSR build ----------------
__global__ void k_zero_cnt(int n) {
    int i = blockIdx.x * blockDim.x + threadIdx.x;
    if (i < n) g_cnt[i] = 0;
}
__global__ void k_count(const void* __restrict__ ei, int E, int n) {
    int i = blockIdx.x * blockDim.x + threadIdx.x;
    if (i < E) {
        int t = edge_at(ei, (size_t)E + i);
        t = max(0, min(n - 1, t));
        atomicAdd(&g_cnt[t], 1);
    }
}
__global__ void k_dinv(int n) {
    int i = blockIdx.x * blockDim.x + threadIdx.x;
    if (i < n) g_dinv[i] = rsqrtf((float)(g_cnt[i] + 1));
}
__global__ void k_scan1(int n) {
    __shared__ int s[SCAN_B];
    int i = blockIdx.x * SCAN_B + threadIdx.x;
    int v = (i < n) ? g_cnt[i] : 0;
    s[threadIdx.x] = v;
    __syncthreads();
#pragma unroll
    for (int d = 1; d < SCAN_B; d <<= 1) {
        int t = (threadIdx.x >= d) ? s[threadIdx.x - d] : 0;
        __syncthreads();
        s[threadIdx.x] += t;
        __syncthreads();
    }
    if (i < n) g_offs[i] = s[threadIdx.x] - v;
    if (threadIdx.x == SCAN_B - 1) g_bsum[blockIdx.x] = s[threadIdx.x];
}
__global__ void k_scan2(int nb) {
    __shared__ int s[256];
    int v = (threadIdx.x < nb) ? g_bsum[threadIdx.x] : 0;
    s[threadIdx.x] = v;
    __syncthreads();
#pragma unroll
    for (int d = 1; d < 256; d <<= 1) {
        int t = (threadIdx.x >= d) ? s[threadIdx.x - d] : 0;
        __syncthreads();
        s[threadIdx.x] += t;
        __syncthreads();
    }
    if (threadIdx.x < nb) g_bsum[threadIdx.x] = s[threadIdx.x] - v;
}
__global__ void k_scan3(int n, int E) {
    int i = blockIdx.x * blockDim.x + threadIdx.x;
    if (i < n) {
        int o = g_offs[i] + g_bsum[i / SCAN_B];
        g_offs[i] = o;
        g_cur[i]  = o;
    }
    if (i == 0) g_offs[n] = E;
}
__global__ void k_fill(const void* __restrict__ ei, int E, int n) {
    int e = blockIdx.x * blockDim.x + threadIdx.x;
    if (e >= E) return;
    int r = edge_at(ei, e);
    int c = edge_at(ei, (size_t)E + e);
    r = max(0, min(n - 1, r));
    c = max(0, min(n - 1, c));
    int pos = atomicAdd(&g_cur[c], 1);
    g_esrc[pos] = r;
}

// ---------------- warp-per-node gather ----------------
__global__ void k_gather(const float* __restrict__ b, int n) {
    int node = (blockIdx.x * blockDim.x + threadIdx.x) >> 5;
    int lane = threadIdx.x & 31;
    if (node >= n) return;
    const float dc = g_dinv[node];
    const int beg = g_offs[node], end = g_offs[node + 1];

    const __half2* selfrow = reinterpret_cast<const __half2*>(g_xwf + (size_t)node * G_CH);
    float2 s0 = __half22float2(selfrow[lane]);
    float2 s1 = __half22float2(selfrow[lane + 32]);
    float ws = dc * dc;
    float a0 = s0.x * ws, a1 = s0.y * ws, a2 = s1.x * ws, a3 = s1.y * ws;

    for (int e = beg; e < end; e++) {
        int r = g_esrc[e];
        float w = g_dinv[r] * dc;
        const __half2* src = reinterpret_cast<const __half2*>(g_xwf + (size_t)r * G_CH);
        float2 f0 = __half22float2(src[lane]);
        float2 f1 = __half22float2(src[lane + 32]);
        a0 = fmaf(f0.x, w, a0); a1 = fmaf(f0.y, w, a1);
        a2 = fmaf(f1.x, w, a2); a3 = fmaf(f1.y, w, a3);
    }
    int c0 = 2 * lane, c1 = 2 * (lane + 32);
    a0 = fmaxf(a0 + __ldg(&b[c0]),     0.0f);
    a1 = fmaxf(a1 + __ldg(&b[c0 + 1]), 0.0f);
    a2 = fmaxf(a2 + __ldg(&b[c1]),     0.0f);
    a3 = fmaxf(a3 + __ldg(&b[c1 + 1]), 0.0f);
    __half2* dst = reinterpret_cast<__half2*>(g_x1f + (size_t)node * G_CH);
    dst[lane]      = __floats2half2_rn(a0, a1);
    dst[lane + 32] = __floats2half2_rn(a2, a3);
}

// ---------------- launch ----------------
extern "C" void kernel_launch(void* const* d_in, const int* in_sizes, int n_in,
                              void* d_out, int out_size) {
    const float* x     = nullptr;  int x_cnt = 0;
    const void*  ei    = nullptr;  int ei_cnt = 0;
    const float* W_gcn = nullptr;
    const float* b_gcn = nullptr;
    const float* W_hid = nullptr;
    const float* b_hid = nullptr;
    const float* W_cls = nullptr;
    const float* b_cls = nullptr;

    int max_cnt = 0;
    for (int i = 0; i < n_in; i++) if (in_sizes[i] > max_cnt) max_cnt = in_sizes[i];
    for (int i = 0; i < n_in; i++) {
        int c = in_sizes[i];
        if      (c == IN_CH * G_CH)  W_gcn = (const float*)d_in[i];
        else if (c == KCAT * HID)    W_hid = (const float*)d_in[i];
        else if (c == HID * NCLS)    W_cls = (const float*)d_in[i];
        else if (c == G_CH)          b_gcn = (const float*)d_in[i];
        else if (c == HID)           b_hid = (const float*)d_in[i];
        else if (c == NCLS)          b_cls = (const float*)d_in[i];
        else if (c == max_cnt && c % IN_CH == 0) { x = (const float*)d_in[i]; x_cnt = c; }
    }
    const int N = x_cnt / IN_CH;

    for (int i = 0; i < n_in; i++) {
        const void* p = d_in[i];
        if (p == (const void*)x || p == (const void*)W_gcn || p == (const void*)W_hid ||
            p == (const void*)W_cls || p == (const void*)b_gcn || p == (const void*)b_hid ||
            p == (const void*)b_cls) continue;
        int c = in_sizes[i];
        if (c != 2 * N) { ei = p; ei_cnt = c; }
        else if (ei == nullptr) { ei = p; ei_cnt = c; }
    }
    const int E = ei_cnt / 2;

    float* h      = (float*)d_out;
    float* logits = h + (size_t)N * HID;

    const int mblocks = (N + 127) / 128;
    const int nscan   = (N + SCAN_B - 1) / SCAN_B;

    // 0) probes + weight conversions
    k_detect<<<1, 32>>>(ei, E, N);
    k_conv_w<0><<<(G_CH * IN_CH + 255) / 256, 256>>>(W_gcn);
    k_conv_w<1><<<(HID * KCAT + 255) / 256, 256>>>(W_hid);
    k_conv_w<2><<<(128 * HID + 255) / 256, 256>>>(W_cls);

    // 1) fused: xw = x @ W_gcn -> g_xwf, AND x -> g_xf (fp16)
    tc_gemm<true, 0, 0, false, false, false, 1>
        <<<dim3(mblocks, 1), 256, SMEM_DYN>>>(x, nullptr, nullptr, N, G_CH);

    // 2) CSR build
    k_zero_cnt<<<(N + 255) / 256, 256>>>(N);
    k_count<<<(E + 255) / 256, 256>>>(ei, E, N);
    k_dinv<<<(N + 255) / 256, 256>>>(N);
    k_scan1<<<nscan, SCAN_B>>>(N);
    k_scan2<<<1, 256>>>(nscan);
    k_scan3<<<(N + 255) / 256, 256>>>(N, E);
    k_fill<<<(E + 255) / 256, 256>>>(ei, E, N);

    // 3) gather-aggregate -> x1 fp16
    k_gather<<<(N * 32 + 255) / 256, 256>>>(b_gcn, N);

    // 4) h = relu([x | x1] @ W_hid + b_hid) -> d_out (+ fp16 plane); n-fast grid
    tc_gemm<false, 1, 1, true, true, true, 0>
        <<<dim3(4, mblocks), 256, SMEM_DYN>>>(nullptr, b_hid, h, N, HID);

    // 5) logits = h @ W_cls + b_cls
    tc_gemm<false, 2, 2, true, false, false, 0>
        <<<dim3(mblocks, 1), 256, SMEM_DYN>>>(nullptr, b_cls, logits, N, NCLS);
}

// round 15
// speedup vs baseline: 10.9385x; 1.0960x over previous
#include <cuda_runtime.h>
#include <cuda_fp16.h>
#include <cstdint>

#define N_NODES 100000
#define N_PAD   100096
#define E_MAX   700000
#define IN_CH   1280
#define G_CH    128
#define HID     512
#define NCLS    79
#define KCAT    (IN_CH + G_CH)
#define SCAN_B  512

// ---------------- scratch (device globals; no allocation allowed) ----------------
__device__ float  g_dinv[N_NODES];
__device__ int    g_cnt [N_NODES];
__device__ int    g_offs[N_NODES + 1];
__device__ int    g_cur [N_NODES];
__device__ int    g_bsum[256];
__device__ int    g_esrc[E_MAX];
__device__ int    g_i64mode;
__device__ __half g_xwf[(size_t)N_PAD * G_CH];    // x @ W_gcn (fp16)
__device__ __half g_xf [(size_t)N_PAD * IN_CH];   // fp16 x (written by fused GEMM1)
__device__ __half g_x1f[(size_t)N_PAD * G_CH];
__device__ __half g_wgf[G_CH * IN_CH];
__device__ __half g_whf[HID * KCAT];
__device__ __half g_wcf[128 * HID];

// ---------------- PTX helpers ----------------
__device__ __forceinline__ uint32_t smem_u32(const void* p) {
    uint32_t a;
    asm("{ .reg .u64 t; cvta.to.shared.u64 t, %1; cvt.u32.u64 %0, t; }" : "=r"(a) : "l"(p));
    return a;
}
__device__ __forceinline__ void cp16(uint32_t dst, const void* src) {
    asm volatile("cp.async.cg.shared.global [%0], [%1], 16;" :: "r"(dst), "l"(src));
}
__device__ __forceinline__ void ldm_x4(uint32_t* r, uint32_t addr) {
    asm volatile("ldmatrix.sync.aligned.m8n8.x4.shared.b16 {%0,%1,%2,%3}, [%4];"
        : "=r"(r[0]), "=r"(r[1]), "=r"(r[2]), "=r"(r[3]) : "r"(addr));
}
__device__ __forceinline__ void mma16816(float* c, const uint32_t* a, const uint32_t* b) {
    asm volatile("mma.sync.aligned.m16n8k16.row.col.f32.f16.f16.f32 "
        "{%0,%1,%2,%3}, {%4,%5,%6,%7}, {%8,%9}, {%0,%1,%2,%3};"
        : "+f"(c[0]), "+f"(c[1]), "+f"(c[2]), "+f"(c[3])
        : "r"(a[0]), "r"(a[1]), "r"(a[2]), "r"(a[3]), "r"(b[0]), "r"(b[1]));
}
__device__ __forceinline__ void sts16(uint32_t addr, uint32_t a, uint32_t b, uint32_t c, uint32_t d) {
    asm volatile("st.shared.v4.b32 [%0], {%1,%2,%3,%4};" :: "r"(addr), "r"(a), "r"(b), "r"(c), "r"(d));
}
__device__ __forceinline__ uint32_t pack2(float a, float b) {
    __half2 h = __floats2half2_rn(a, b);
    return *reinterpret_cast<uint32_t*>(&h);
}

// ---------------- combined prep: convert all weights + zero g_cnt ----------------
#define WG_TOT (G_CH * IN_CH)
#define WH_TOT (HID * KCAT)
#define WC_TOT (128 * HID)
__global__ void k_prep(const float* __restrict__ Wg, const float* __restrict__ Wh,
                       const float* __restrict__ Wc, int n) {
    int idx = blockIdx.x * blockDim.x + threadIdx.x;
    if (idx < WG_TOT) {
        int nn = idx / IN_CH, k = idx % IN_CH;
        g_wgf[idx] = __float2half_rn(__ldg(&Wg[(size_t)k * G_CH + nn]));
        return;
    }
    idx -= WG_TOT;
    if (idx < WH_TOT) {
        int nn = idx / KCAT, k = idx % KCAT;
        g_whf[idx] = __float2half_rn(__ldg(&Wh[(size_t)k * HID + nn]));
        return;
    }
    idx -= WH_TOT;
    if (idx < WC_TOT) {
        int nn = idx / HID, k = idx % HID;
        float v = (nn < NCLS) ? __ldg(&Wc[(size_t)k * NCLS + nn]) : 0.0f;
        g_wcf[idx] = __float2half_rn(v);
        return;
    }
    idx -= WC_TOT;
    if (idx < n) g_cnt[idx] = 0;
}

// ---------------- pipelined fp16 tensor-core GEMM ----------------
// AFUSE: A read as fp32 from Afp32 (stride = K), converted in regs; MIRROR: also
//        store fp16 A to g_xf. Otherwise A via cp.async from fp16 planes.
// BK: k-chunk (32 or 64). AM: 0 = x, 1 = [x|x1], 2 = unused-with-AFUSE
// BMODE: 0/1/2 = W_gcn/W_hid/W_cls. CM: 0 -> Cp fp32, 1 -> g_xwf fp16.
// HOUT: vectorized fp32 store (Nout mult of 2), n-fast grid.
template<bool AFUSE, bool MIRROR, int BK, int AM, int BMODE,
         bool BIAS, bool RELU, bool HOUT, int CM>
__global__ void __launch_bounds__(256, 2)
tc_gemm(const float* __restrict__ Afp32, const float* __restrict__ bias,
        float* __restrict__ Cp, int M, int Nout)
{
    constexpr int RS    = BK + 8;
    constexpr int PLANE = 128 * RS * 2;
    constexpr int STAGE = 2 * PLANE;
    constexpr int GRP   = BK / 8;      // 16B groups per row
    constexpr int IT    = BK / 16;     // per-thread copies per plane

    extern __shared__ __align__(16) char dsm[];
    const uint32_t base = smem_u32(dsm);

    const int tid  = threadIdx.x;
    const int wid  = tid >> 5;
    const int lane = tid & 31;
    const int wm = wid >> 2;
    const int wn = wid & 3;
    const int m0 = (HOUT ? blockIdx.y : blockIdx.x) * 128;
    const int n0 = (HOUT ? blockIdx.x : blockIdx.y) * 128;

    float acc[4][4][4];
#pragma unroll
    for (int i = 0; i < 4; i++)
#pragma unroll
        for (int j = 0; j < 4; j++)
#pragma unroll
            for (int r = 0; r < 4; r++) acc[i][j][r] = 0.0f;

    constexpr int K  = (AM == 0) ? IN_CH : (AM == 1) ? KCAT : HID;
    constexpr int Kb = (BMODE == 0) ? IN_CH : (BMODE == 1) ? KCAT : HID;
    constexpr int nchunks = K / BK;

    const int lrow = lane & 15;
    const int lko  = (lane >> 4) << 3;

    auto issueB = [&](int ch, int stg) {
        const int k0 = ch * BK;
        const __half* pB = (BMODE == 0) ? g_wgf : (BMODE == 1) ? g_whf : g_wcf;
        const uint32_t sb = base + stg * STAGE + PLANE;
#pragma unroll
        for (int it = 0; it < IT; it++) {
            int o = tid + it * 256;
            int row = o / GRP, grp = o % GRP;
            cp16(sb + (uint32_t)(row * (RS * 2) + grp * 16),
                 pB + (size_t)(n0 + row) * Kb + k0 + grp * 8);
        }
    };
    auto issueA = [&](int ch, int stg) {
        const int k0 = ch * BK;
        const __half* pA; int Kd, koff;
        if (AM == 0) { pA = g_xf; Kd = IN_CH; koff = k0; }
        else {
            if (k0 < IN_CH) { pA = g_xf;  Kd = IN_CH; koff = k0; }
            else            { pA = g_x1f; Kd = G_CH;  koff = k0 - IN_CH; }
        }
        const uint32_t sb = base + stg * STAGE;
#pragma unroll
        for (int it = 0; it < IT; it++) {
            int o = tid + it * 256;
            int row = o / GRP, grp = o % GRP;
            cp16(sb + (uint32_t)(row * (RS * 2) + grp * 16),
                 pA + (size_t)(m0 + row) * Kd + koff + grp * 8);
        }
    };
    // fused fp32 A path (BK==32 instantiations only)
    float4 ra[2][2];
    auto loadA = [&](int ch) {
        const int k0 = ch * BK;
#pragma unroll
        for (int it = 0; it < 2; it++) {
            int o = tid + it * 256;
            int row = o / GRP, grp = o % GRP;
            int gm = m0 + row;
            if (gm < M) {
                const float4* p = reinterpret_cast<const float4*>(
                    Afp32 + (size_t)gm * K + k0 + grp * 8);
                ra[it][0] = p[0];
                ra[it][1] = p[1];
            } else {
                ra[it][0] = make_float4(0.f, 0.f, 0.f, 0.f);
                ra[it][1] = make_float4(0.f, 0.f, 0.f, 0.f);
            }
        }
    };
    auto storeA = [&](int ch, int stg) {
        const int k0 = ch * BK;
        const uint32_t sb = base + stg * STAGE;
#pragma unroll
        for (int it = 0; it < 2; it++) {
            int o = tid + it * 256;
            int row = o / GRP, grp = o % GRP;
            uint32_t h0 = pack2(ra[it][0].x, ra[it][0].y);
            uint32_t h1 = pack2(ra[it][0].z, ra[it][0].w);
            uint32_t h2 = pack2(ra[it][1].x, ra[it][1].y);
            uint32_t h3 = pack2(ra[it][1].z, ra[it][1].w);
            sts16(sb + (uint32_t)(row * (RS * 2) + grp * 16), h0, h1, h2, h3);
            if (MIRROR) {
                uint4* dst = reinterpret_cast<uint4*>(
                    g_xf + (size_t)(m0 + row) * IN_CH + k0 + grp * 8);
                *dst = make_uint4(h0, h1, h2, h3);
            }
        }
    };

    // ---- prologue ----
    if (AFUSE) {
        loadA(0);
        issueB(0, 0);
        asm volatile("cp.async.commit_group;");
        storeA(0, 0);
        asm volatile("cp.async.wait_group 0;");
        __syncthreads();
    } else {
        issueA(0, 0); issueB(0, 0);
        asm volatile("cp.async.commit_group;");
    }

    for (int ch = 0; ch < nchunks; ch++) {
        const int stg = ch & 1;
        if (AFUSE) {
            if (ch + 1 < nchunks) { loadA(ch + 1); issueB(ch + 1, stg ^ 1);
                                    asm volatile("cp.async.commit_group;"); }
        } else {
            if (ch + 1 < nchunks) {
                issueA(ch + 1, stg ^ 1); issueB(ch + 1, stg ^ 1);
                asm volatile("cp.async.commit_group;");
                asm volatile("cp.async.wait_group 1;");
            } else {
                asm volatile("cp.async.wait_group 0;");
            }
            __syncthreads();
        }

        const uint32_t uA = base + stg * STAGE;
        const uint32_t uB = uA + PLANE;

#pragma unroll
        for (int s = 0; s < BK / 16; s++) {
            const int ks = s * 16 + lko;
            uint32_t bt[4][2];
#pragma unroll
            for (int g = 0; g < 2; g++) {
                uint32_t r[4];
                uint32_t addr = uB + ((wn * 32 + g * 16 + lrow) * RS + ks) * 2;
                ldm_x4(r, addr);
                bt[2 * g][0] = r[0]; bt[2 * g][1] = r[2];
                bt[2 * g + 1][0] = r[1]; bt[2 * g + 1][1] = r[3];
            }
            uint32_t at[4][4];
#pragma unroll
            for (int mt = 0; mt < 4; mt++) {
                uint32_t addr = uA + ((wm * 64 + mt * 16 + lrow) * RS + ks) * 2;
                ldm_x4(at[mt], addr);
            }
#pragma unroll
            for (int mt = 0; mt < 4; mt++)
#pragma unroll
                for (int nt = 0; nt < 4; nt++)
                    mma16816(acc[mt][nt], at[mt], bt[nt]);
        }

        if (AFUSE) {
            if (ch + 1 < nchunks) {
                storeA(ch + 1, stg ^ 1);
                asm volatile("cp.async.wait_group 0;");
            }
            __syncthreads();
        } else {
            __syncthreads();
        }
    }

    // ---- epilogue ----
    const int qr = lane >> 2;
    const int qc = (lane & 3) * 2;
#pragma unroll
    for (int mt = 0; mt < 4; mt++) {
#pragma unroll
        for (int nt = 0; nt < 4; nt++) {
#pragma unroll
            for (int half = 0; half < 2; half++) {
                int gm = m0 + wm * 64 + mt * 16 + qr + half * 8;
                if (gm >= M) continue;
                int gn0 = n0 + wn * 32 + nt * 8 + qc;
                float v0 = acc[mt][nt][half * 2 + 0];
                float v1 = acc[mt][nt][half * 2 + 1];
                if (BIAS) { v0 += __ldg(&bias[gn0]); v1 += __ldg(&bias[gn0 + 1]); }
                if (RELU) { v0 = fmaxf(v0, 0.0f); v1 = fmaxf(v1, 0.0f); }
                if (CM == 1) {
                    *reinterpret_cast<__half2*>(&g_xwf[(size_t)gm * G_CH + gn0]) =
                        __floats2half2_rn(v0, v1);
                } else if (HOUT) {
                    *reinterpret_cast<float2*>(&Cp[(size_t)gm * Nout + gn0]) =
                        make_float2(v0, v1);
                } else {
                    if (gn0 < Nout)     Cp[(size_t)gm * Nout + gn0]     = v0;
                    if (gn0 + 1 < Nout) Cp[(size_t)gm * Nout + gn0 + 1] = v1;
                }
            }
        }
    }
}

// ---------------- edge dtype probe ----------------
__global__ void k_detect(const void* ei_raw, int E, int n) {
    if (threadIdx.x == 0 && blockIdx.x == 0) {
        const long long* p = (const long long*)ei_raw;
        int bad = 0;
        int samples = E < 512 ? E : 512;
        for (int i = 0; i < samples; i++) {
            long long v = p[i];
            if (v < 0 || v >= n) { bad = 1; break; }
        }
        g_i64mode = bad ? 0 : 1;
    }
}
__device__ __forceinline__ int edge_at(const void* ei_raw, size_t idx) {
    if (g_i64mode) return (int)((const long long*)ei_raw)[idx];
    return ((const int*)ei_raw)[idx];
}

// ---------------- CSR build ----------------
__global__ void k_count(const void* __restrict__ ei, int E, int n) {
    int i = blockIdx.x * blockDim.x + threadIdx.x;
    if (i < E) {
        int t = edge_at(ei, (size_t)E + i);
        t = max(0, min(n - 1, t));
        atomicAdd(&g_cnt[t], 1);
    }
}
__global__ void k_dinv(int n) {
    int i = blockIdx.x * blockDim.x + threadIdx.x;
    if (i < n) g_dinv[i] = rsqrtf((float)(g_cnt[i] + 1));
}
__global__ void k_scan1(int n) {
    __shared__ int s[SCAN_B];
    int i = blockIdx.x * SCAN_B + threadIdx.x;
    int v = (i < n) ? g_cnt[i] : 0;
    s[threadIdx.x] = v;
    __syncthreads();
#pragma unroll
    for (int d = 1; d < SCAN_B; d <<= 1) {
        int t = (threadIdx.x >= d) ? s[threadIdx.x - d] : 0;
        __syncthreads();
        s[threadIdx.x] += t;
        __syncthreads();
    }
    if (i < n) g_offs[i] = s[threadIdx.x] - v;
    if (threadIdx.x == SCAN_B - 1) g_bsum[blockIdx.x] = s[threadIdx.x];
}
__global__ void k_scan2(int nb) {
    __shared__ int s[256];
    int v = (threadIdx.x < nb) ? g_bsum[threadIdx.x] : 0;
    s[threadIdx.x] = v;
    __syncthreads();
#pragma unroll
    for (int d = 1; d < 256; d <<= 1) {
        int t = (threadIdx.x >= d) ? s[threadIdx.x - d] : 0;
        __syncthreads();
        s[threadIdx.x] += t;
        __syncthreads();
    }
    if (threadIdx.x < nb) g_bsum[threadIdx.x] = s[threadIdx.x] - v;
}
__global__ void k_scan3(int n, int E) {
    int i = blockIdx.x * blockDim.x + threadIdx.x;
    if (i < n) {
        int o = g_offs[i] + g_bsum[i / SCAN_B];
        g_offs[i] = o;
        g_cur[i]  = o;
    }
    if (i == 0) g_offs[n] = E;
}
__global__ void k_fill(const void* __restrict__ ei, int E, int n) {
    int e = blockIdx.x * blockDim.x + threadIdx.x;
    if (e >= E) return;
    int r = edge_at(ei, e);
    int c = edge_at(ei, (size_t)E + e);
    r = max(0, min(n - 1, r));
    c = max(0, min(n - 1, c));
    int pos = atomicAdd(&g_cur[c], 1);
    g_esrc[pos] = r;
}

// ---------------- warp-per-node gather ----------------
__global__ void k_gather(const float* __restrict__ b, int n) {
    int node = (blockIdx.x * blockDim.x + threadIdx.x) >> 5;
    int lane = threadIdx.x & 31;
    if (node >= n) return;
    const float dc = g_dinv[node];
    const int beg = g_offs[node], end = g_offs[node + 1];

    const __half2* selfrow = reinterpret_cast<const __half2*>(g_xwf + (size_t)node * G_CH);
    float2 s0 = __half22float2(selfrow[lane]);
    float2 s1 = __half22float2(selfrow[lane + 32]);
    float ws = dc * dc;
    float a0 = s0.x * ws, a1 = s0.y * ws, a2 = s1.x * ws, a3 = s1.y * ws;

    for (int e = beg; e < end; e++) {
        int r = g_esrc[e];
        float w = g_dinv[r] * dc;
        const __half2* src = reinterpret_cast<const __half2*>(g_xwf + (size_t)r * G_CH);
        float2 f0 = __half22float2(src[lane]);
        float2 f1 = __half22float2(src[lane + 32]);
        a0 = fmaf(f0.x, w, a0); a1 = fmaf(f0.y, w, a1);
        a2 = fmaf(f1.x, w, a2); a3 = fmaf(f1.y, w, a3);
    }
    int c0 = 2 * lane, c1 = 2 * (lane + 32);
    a0 = fmaxf(a0 + __ldg(&b[c0]),     0.0f);
    a1 = fmaxf(a1 + __ldg(&b[c0 + 1]), 0.0f);
    a2 = fmaxf(a2 + __ldg(&b[c1]),     0.0f);
    a3 = fmaxf(a3 + __ldg(&b[c1 + 1]), 0.0f);
    __half2* dst = reinterpret_cast<__half2*>(g_x1f + (size_t)node * G_CH);
    dst[lane]      = __floats2half2_rn(a0, a1);
    dst[lane + 32] = __floats2half2_rn(a2, a3);
}

// ---------------- launch ----------------
#define SMEM_32 (2 * 2 * 128 * (32 + 8) * 2)   // 40960
#define SMEM_64 (2 * 2 * 128 * (64 + 8) * 2)   // 73728

extern "C" void kernel_launch(void* const* d_in, const int* in_sizes, int n_in,
                              void* d_out, int out_size) {
    const float* x     = nullptr;  int x_cnt = 0;
    const void*  ei    = nullptr;  int ei_cnt = 0;
    const float* W_gcn = nullptr;
    const float* b_gcn = nullptr;
    const float* W_hid = nullptr;
    const float* b_hid = nullptr;
    const float* W_cls = nullptr;
    const float* b_cls = nullptr;

    int max_cnt = 0;
    for (int i = 0; i < n_in; i++) if (in_sizes[i] > max_cnt) max_cnt = in_sizes[i];
    for (int i = 0; i < n_in; i++) {
        int c = in_sizes[i];
        if      (c == IN_CH * G_CH)  W_gcn = (const float*)d_in[i];
        else if (c == KCAT * HID)    W_hid = (const float*)d_in[i];
        else if (c == HID * NCLS)    W_cls = (const float*)d_in[i];
        else if (c == G_CH)          b_gcn = (const float*)d_in[i];
        else if (c == HID)           b_hid = (const float*)d_in[i];
        else if (c == NCLS)          b_cls = (const float*)d_in[i];
        else if (c == max_cnt && c % IN_CH == 0) { x = (const float*)d_in[i]; x_cnt = c; }
    }
    const int N = x_cnt / IN_CH;

    for (int i = 0; i < n_in; i++) {
        const void* p = d_in[i];
        if (p == (const void*)x || p == (const void*)W_gcn || p == (const void*)W_hid ||
            p == (const void*)W_cls || p == (const void*)b_gcn || p == (const void*)b_hid ||
            p == (const void*)b_cls) continue;
        int c = in_sizes[i];
        if (c != 2 * N) { ei = p; ei_cnt = c; }
        else if (ei == nullptr) { ei = p; ei_cnt = c; }
    }
    const int E = ei_cnt / 2;

    float* h      = (float*)d_out;
    float* logits = h + (size_t)N * HID;

    const int mblocks = (N + 127) / 128;
    const int nscan   = (N + SCAN_B - 1) / SCAN_B;

    // raise dynamic smem cap for the BK=64 GEMM2 (capture-safe; proven R9)
    cudaFuncSetAttribute(tc_gemm<false, false, 64, 1, 1, true, true, true, 0>,
                         cudaFuncAttributeMaxDynamicSharedMemorySize, SMEM_64);

    // 0) probe + combined prep (weights + cnt zero)
    k_detect<<<1, 32>>>(ei, E, N);
    int prep_tot = WG_TOT + WH_TOT + WC_TOT + N;
    k_prep<<<(prep_tot + 255) / 256, 256>>>(W_gcn, W_hid, W_cls, N);

    // 1) fused: xw = x @ W_gcn -> g_xwf, AND x -> g_xf (fp16)
    tc_gemm<true, true, 32, 0, 0, false, false, false, 1>
        <<<dim3(mblocks, 1), 256, SMEM_32>>>(x, nullptr, nullptr, N, G_CH);

    // 2) CSR build
    k_count<<<(E + 255) / 256, 256>>>(ei, E, N);
    k_dinv<<<(N + 255) / 256, 256>>>(N);
    k_scan1<<<nscan, SCAN_B>>>(N);
    k_scan2<<<1, 256>>>(nscan);
    k_scan3<<<(N + 255) / 256, 256>>>(N, E);
    k_fill<<<(E + 255) / 256, 256>>>(ei, E, N);

    // 3) gather-aggregate -> x1 fp16
    k_gather<<<(N * 32 + 255) / 256, 256>>>(b_gcn, N);

    // 4) h = relu([x | x1] @ W_hid + b_hid) -> d_out; n-fast grid, BK=64
    tc_gemm<false, false, 64, 1, 1, true, true, true, 0>
        <<<dim3(4, mblocks), 256, SMEM_64>>>(nullptr, b_hid, h, N, HID);

    // 5) logits = h @ W_cls + b_cls (reads fp32 h from d_out, no mirror)
    tc_gemm<true, false, 32, 2, 2, true, false, false, 0>
        <<<dim3(mblocks, 1), 256, SMEM_32>>>(h, b_cls, logits, N, NCLS);
}